// round 13
// baseline (speedup 1.0000x reference)
#include <cuda_runtime.h>
#include <cuda_fp16.h>
#include <cstdint>

#define NMAX 100000
#define EMAX 1600000
#define BMAX 512
#define ROWH 136                     // fp16 tile row stride (halves)
static const size_t XH_STRIDE = (size_t)NMAX * 128;

// ---------------- device scratch ----------------
__device__ __half g_xh[(size_t)3 * NMAX * 128];
__device__ __half g_hv[(size_t)3 * NMAX * 128];
__device__ unsigned g_xq[(size_t)3 * NMAX * 32];   // int8 rows: 32 u32/node
__device__ float2 g_combo[3 * NMAX * 4];            // {asrc[h], scale[h]} x4 per node
__device__ float g_asrc[3 * NMAX * 4];
__device__ float g_adst[3 * NMAX * 4];
__device__ float g_eg[3 * NMAX];
__device__ int   g_cnt[3 * NMAX];
__device__ int   g_start[3 * NMAX];
__device__ int   g_cursor[3 * NMAX];
__device__ int   g_col[3 * EMAX];
__device__ int   g_gs[BMAX];
__device__ int   g_ge[BMAX];
__device__ float g_combined[(size_t)BMAX * 384];
__device__ unsigned g_Wfrag16[4 * 8192];
__device__ float g_attc[3 * 2 * 128];
// lookback scan state (zeroed each replay)
__device__ int g_scan_flag[512];
__device__ int g_scan_agg[512];
__device__ int g_scan_pfx[512];

// signed byte extract (aarch64 host: plain `char` is unsigned — must sign-extend explicitly)
__device__ __forceinline__ float sb0(unsigned u) { return (float)((int)(u << 24) >> 24); }
__device__ __forceinline__ float sb1(unsigned u) { return (float)((int)(u << 16) >> 24); }
__device__ __forceinline__ float sb2(unsigned u) { return (float)((int)(u <<  8) >> 24); }
__device__ __forceinline__ float sb3(unsigned u) { return (float)((int)u >> 24); }

// ---------------- mma helpers ----------------
__device__ __forceinline__ void mma_f16(float* d, const unsigned* a, const unsigned* b) {
    asm volatile(
        "mma.sync.aligned.m16n8k16.row.col.f32.f16.f16.f32 "
        "{%0,%1,%2,%3},{%4,%5,%6,%7},{%8,%9},{%0,%1,%2,%3};"
        : "+f"(d[0]), "+f"(d[1]), "+f"(d[2]), "+f"(d[3])
        : "r"(a[0]), "r"(a[1]), "r"(a[2]), "r"(a[3]), "r"(b[0]), "r"(b[1]));
}

__device__ __forceinline__ void ldsm_x4(unsigned* a, uint32_t addr) {
    asm volatile("ldmatrix.sync.aligned.m8n8.x4.shared.b16 {%0,%1,%2,%3}, [%4];"
                 : "=r"(a[0]), "=r"(a[1]), "=r"(a[2]), "=r"(a[3]) : "r"(addr));
}

// ---------------- prep: fp16 fragment-reorder weights, pack att vecs ----------------
__global__ void prep_kernel(
    const float* __restrict__ pw,
    const float* __restrict__ w0, const float* __restrict__ w1, const float* __restrict__ w2,
    const float* __restrict__ as0, const float* __restrict__ ad0,
    const float* __restrict__ as1, const float* __restrict__ ad1,
    const float* __restrict__ as2, const float* __restrict__ ad2,
    unsigned* __restrict__ Wfrag, float* __restrict__ attc)
{
    int i = blockIdx.x * blockDim.x + threadIdx.x;
    if (i < 32768) {
        int breg = i & 1;
        int lane = (i >> 1) & 31;
        int ntg  = (i >> 6) & 15;
        int kt   = (i >> 10) & 7;
        int m    = i >> 13;
        int t = lane & 3, nr = lane >> 2;
        int n = ntg * 8 + nr;
        int k = kt * 16 + 2 * t + breg * 8;
        const float* Wm = (m == 0) ? pw : (m == 1) ? w0 : (m == 2) ? w1 : w2;
        __half lo = __float2half(Wm[k * 128 + n]);
        __half hi = __float2half(Wm[(k + 1) * 128 + n]);
        __half2 h2 = __halves2half2(lo, hi);
        Wfrag[i] = *(unsigned*)&h2;
    } else if (i < 32768 + 768) {
        int j = i - 32768;
        int v = j >> 8;
        int rem = j & 255;
        int sd = rem >> 7;
        int c = rem & 127;
        const float* p;
        if (v == 0) p = sd ? ad0 : as0;
        else if (v == 1) p = sd ? ad1 : as1;
        else p = sd ? ad2 : as2;
        attc[j] = p[c];
    }
}

// ---------------- fused front: LN + proj + 3 view GEMMs + att coefs ----------------
__global__ void __launch_bounds__(256) fused_front_kernel(
    const float* __restrict__ x, const float* __restrict__ ln_g, const float* __restrict__ ln_b,
    const unsigned* __restrict__ Wfrag, const float* __restrict__ proj_b,
    const float* __restrict__ attc,
    __half* __restrict__ xh, float* __restrict__ asrc, float* __restrict__ adst, int n)
{
    __shared__ __align__(16) __half sH[64 * ROWH];
    int t = threadIdx.x;
    int lane = t & 31, w = t >> 5;
    int wr = w >> 2, wc = w & 3;
    int base = blockIdx.x * 64;

    {
        float4 lng = *(const float4*)(ln_g + lane * 4);
        float4 lnb = *(const float4*)(ln_b + lane * 4);
        #pragma unroll
        for (int jj = 0; jj < 8; jj++) {
            int j = w * 8 + jj;
            int node = base + j;
            float4 v = make_float4(0.f, 0.f, 0.f, 0.f);
            if (node < n) v = *(const float4*)(x + (size_t)node * 128 + lane * 4);
            float s = v.x + v.y + v.z + v.w;
            float q = v.x * v.x + v.y * v.y + v.z * v.z + v.w * v.w;
            #pragma unroll
            for (int o = 16; o; o >>= 1) {
                s += __shfl_xor_sync(0xffffffffu, s, o);
                q += __shfl_xor_sync(0xffffffffu, q, o);
            }
            float mu = s * (1.f / 128.f);
            float var = q * (1.f / 128.f) - mu * mu;
            float inv = rsqrtf(var + 1e-5f);
            float n0 = (v.x - mu) * inv * lng.x + lnb.x;
            float n1 = (v.y - mu) * inv * lng.y + lnb.y;
            float n2 = (v.z - mu) * inv * lng.z + lnb.z;
            float n3 = (v.w - mu) * inv * lng.w + lnb.w;
            __half2 h0 = __floats2half2_rn(n0, n1);
            __half2 h1 = __floats2half2_rn(n2, n3);
            uint2 pk;
            pk.x = *(unsigned*)&h0;
            pk.y = *(unsigned*)&h1;
            *(uint2*)(sH + j * ROWH + lane * 4) = pk;
        }
    }
    __syncthreads();

    uint32_t sH_u = (uint32_t)__cvta_generic_to_shared(sH);
    int g8 = lane >> 3;
    int lrow = (lane & 7) + ((g8 & 1) << 3);
    int koff = (g8 >> 1) << 3;
    uint32_t abase[2];
    abase[0] = sH_u + (uint32_t)(((wr * 32 + lrow) * ROWH + koff) * 2);
    abase[1] = sH_u + (uint32_t)(((wr * 32 + 16 + lrow) * ROWH + koff) * 2);

    float acc[8][4];

    // ---- GEMM 1: proj ----
    {
        #pragma unroll
        for (int i = 0; i < 8; i++) { acc[i][0] = acc[i][1] = acc[i][2] = acc[i][3] = 0.f; }
        const unsigned* WF = Wfrag;
        #pragma unroll
        for (int kt = 0; kt < 8; kt++) {
            unsigned a[2][4];
            ldsm_x4(a[0], abase[0] + kt * 32);
            ldsm_x4(a[1], abase[1] + kt * 32);
            uint2 b[4];
            #pragma unroll
            for (int nt = 0; nt < 4; nt++)
                b[nt] = *(const uint2*)&WF[(kt * 16 + (wc * 4 + nt)) * 64 + lane * 2];
            #pragma unroll
            for (int mt = 0; mt < 2; mt++)
                #pragma unroll
                for (int nt = 0; nt < 4; nt++)
                    mma_f16(acc[mt * 4 + nt], a[mt], (const unsigned*)&b[nt]);
        }
    }
    __syncthreads();

    #pragma unroll
    for (int mt = 0; mt < 2; mt++) {
        #pragma unroll
        for (int nt = 0; nt < 4; nt++) {
            float* c = acc[mt * 4 + nt];
            int r0 = wr * 32 + mt * 16 + (lane >> 2);
            int c0 = wc * 32 + nt * 8 + (lane & 3) * 2;
            float pb0 = proj_b[c0], pb1 = proj_b[c0 + 1];
            float v0 = c[0] + pb0, v1 = c[1] + pb1, v2 = c[2] + pb0, v3 = c[3] + pb1;
            v0 = (v0 > 0.f) ? v0 : 0.01f * v0;
            v1 = (v1 > 0.f) ? v1 : 0.01f * v1;
            v2 = (v2 > 0.f) ? v2 : 0.01f * v2;
            v3 = (v3 > 0.f) ? v3 : 0.01f * v3;
            *(__half2*)(sH + r0 * ROWH + c0) = __floats2half2_rn(v0, v1);
            *(__half2*)(sH + (r0 + 8) * ROWH + c0) = __floats2half2_rn(v2, v3);
        }
    }
    __syncthreads();

    for (int v = 0; v < 3; v++) {
        const unsigned* WF = Wfrag + (v + 1) * 8192;
        #pragma unroll
        for (int i = 0; i < 8; i++) { acc[i][0] = acc[i][1] = acc[i][2] = acc[i][3] = 0.f; }
        #pragma unroll
        for (int kt = 0; kt < 8; kt++) {
            unsigned a[2][4];
            ldsm_x4(a[0], abase[0] + kt * 32);
            ldsm_x4(a[1], abase[1] + kt * 32);
            uint2 b[4];
            #pragma unroll
            for (int nt = 0; nt < 4; nt++)
                b[nt] = *(const uint2*)&WF[(kt * 16 + (wc * 4 + nt)) * 64 + lane * 2];
            #pragma unroll
            for (int mt = 0; mt < 2; mt++)
                #pragma unroll
                for (int nt = 0; nt < 4; nt++)
                    mma_f16(acc[mt * 4 + nt], a[mt], (const unsigned*)&b[nt]);
        }

        const float* attS = attc + v * 256;
        const float* attD = attS + 128;
        __half* xh_v = xh + (size_t)v * XH_STRIDE;
        float ps[4] = {0.f, 0.f, 0.f, 0.f}, pd[4] = {0.f, 0.f, 0.f, 0.f};
        #pragma unroll
        for (int mt = 0; mt < 2; mt++) {
            #pragma unroll
            for (int nt = 0; nt < 4; nt++) {
                float* c = acc[mt * 4 + nt];
                int r0 = wr * 32 + mt * 16 + (lane >> 2);
                int c0 = wc * 32 + nt * 8 + (lane & 3) * 2;
                int node0 = base + r0, node1 = base + r0 + 8;
                if (node0 < n)
                    *(__half2*)(xh_v + (size_t)node0 * 128 + c0) = __floats2half2_rn(c[0], c[1]);
                if (node1 < n)
                    *(__half2*)(xh_v + (size_t)node1 * 128 + c0) = __floats2half2_rn(c[2], c[3]);
                float s0 = attS[c0], s1 = attS[c0 + 1];
                float d0 = attD[c0], d1 = attD[c0 + 1];
                ps[mt * 2 + 0] += c[0] * s0 + c[1] * s1;
                ps[mt * 2 + 1] += c[2] * s0 + c[3] * s1;
                pd[mt * 2 + 0] += c[0] * d0 + c[1] * d1;
                pd[mt * 2 + 1] += c[2] * d0 + c[3] * d1;
            }
        }
        float* asrc_v = asrc + v * NMAX * 4;
        float* adst_v = adst + v * NMAX * 4;
        #pragma unroll
        for (int idx = 0; idx < 4; idx++) {
            float s = ps[idx], d = pd[idx];
            s += __shfl_xor_sync(0xffffffffu, s, 1);
            s += __shfl_xor_sync(0xffffffffu, s, 2);
            d += __shfl_xor_sync(0xffffffffu, d, 1);
            d += __shfl_xor_sync(0xffffffffu, d, 2);
            if ((lane & 3) == 0) {
                int mt = idx >> 1, half = idx & 1;
                int node = base + wr * 32 + mt * 16 + (lane >> 2) + half * 8;
                if (node < n) {
                    asrc_v[node * 4 + wc] = s;
                    adst_v[node * 4 + wc] = d;
                }
            }
        }
    }
}

// ---------------- quantize: fp16 xh -> int8 rows + {asrc,scale} combo (warp per node) ----------------
__global__ void quant3_kernel(const __half* __restrict__ xh_all, const float* __restrict__ asrc_all,
                              unsigned* __restrict__ xq_all, float2* __restrict__ combo_all, int n)
{
    int d = (blockIdx.x * blockDim.x + threadIdx.x) >> 5;
    int lane = threadIdx.x & 31;
    if (d >= n) return;
    int v = blockIdx.y;
    const uint2* xh2 = (const uint2*)(xh_all + (size_t)v * XH_STRIDE);
    unsigned* xq = xq_all + (size_t)v * NMAX * 32;
    float2* combo = combo_all + v * NMAX * 4;
    const float* asrc = asrc_all + v * NMAX * 4;
    int h = lane >> 3;

    uint2 r = xh2[(size_t)d * 32 + lane];
    float2 f0 = __half22float2(*(const __half2*)&r.x);
    float2 f1 = __half22float2(*(const __half2*)&r.y);
    float m = fmaxf(fmaxf(fabsf(f0.x), fabsf(f0.y)), fmaxf(fabsf(f1.x), fabsf(f1.y)));
    #pragma unroll
    for (int o = 1; o < 8; o <<= 1) m = fmaxf(m, __shfl_xor_sync(0xffffffffu, m, o));
    float scale = m * (1.f / 127.f);
    float invs = (m > 0.f) ? (127.f / m) : 0.f;
    int q0 = __float2int_rn(f0.x * invs);
    int q1 = __float2int_rn(f0.y * invs);
    int q2 = __float2int_rn(f1.x * invs);
    int q3 = __float2int_rn(f1.y * invs);
    unsigned pk = (q0 & 255) | ((q1 & 255) << 8) | ((q2 & 255) << 16) | ((q3 & 255) << 24);
    xq[(size_t)d * 32 + lane] = pk;
    if ((lane & 7) == 0) combo[d * 4 + h] = make_float2(asrc[d * 4 + h], scale);
}

// ---------------- CSR build ----------------
__global__ void zero_kernel(int* cnt, int n_cnt, int* flags, int n_flags) {
    int i = blockIdx.x * blockDim.x + threadIdx.x;
    if (i < n_cnt) cnt[i] = 0;
    if (i < n_flags) flags[i] = 0;
}

__global__ void hist3_kernel(const int* __restrict__ e0, const int* __restrict__ e1,
                             const int* __restrict__ e2, int e, int* __restrict__ cnt)
{
    int v = blockIdx.y;
    const int* dst = ((v == 0) ? e0 : (v == 1) ? e1 : e2) + e;
    int i = blockIdx.x * blockDim.x + threadIdx.x;
    if (i < e) atomicAdd(&cnt[v * NMAX + dst[i]], 1);
}

// ---------------- single-kernel decoupled-lookback scan ----------------
__global__ void __launch_bounds__(256) scan_lookback_kernel(
    const int4* __restrict__ c4, int n4,
    int* __restrict__ start, int* __restrict__ cursor,
    int* flag_, int* agg_, int* pfx_)
{
    volatile int* flag = (volatile int*)flag_;
    volatile int* agg  = (volatile int*)agg_;
    volatile int* pfx  = (volatile int*)pfx_;
    __shared__ int wsum[8];
    __shared__ int s_total;
    __shared__ int s_excl;

    int b = blockIdx.x;
    int t = threadIdx.x, lane = t & 31, w = t >> 5;
    int i = b * 256 + t;
    int4 v = make_int4(0, 0, 0, 0);
    if (i < n4) v = c4[i];
    int s = v.x + v.y + v.z + v.w;
    int incl = s;
    #pragma unroll
    for (int o = 1; o < 32; o <<= 1) {
        int u = __shfl_up_sync(0xffffffffu, incl, o);
        if (lane >= o) incl += u;
    }
    if (lane == 31) wsum[w] = incl;
    if (t == 0) s_excl = 0;
    __syncthreads();
    if (w == 0 && lane < 8) {
        int sv = wsum[lane];
        int si = sv;
        #pragma unroll
        for (int o = 1; o < 8; o <<= 1) {
            int u = __shfl_up_sync(0x000000ffu, si, o);
            if (lane >= o) si += u;
        }
        wsum[lane] = si - sv;
        if (lane == 7) s_total = si;
    }
    __syncthreads();
    int total = s_total;

    if (w == 0) {
        if (b == 0) {
            if (lane == 0) {
                pfx_[0] = total;
                __threadfence();
                flag_[0] = 2;
            }
        } else {
            if (lane == 0) {
                agg_[b] = total;
                __threadfence();
                flag_[b] = 1;
            }
            __syncwarp();
            int excl = 0;
            int pos = b - 1;
            while (true) {
                int idx = pos - lane;
                int f;
                do {
                    f = (idx >= 0) ? flag[idx] : 2;
                } while (!__all_sync(0xffffffffu, f >= 1));
                __threadfence();
                int vv = 0;
                if (idx >= 0) vv = (f == 2) ? pfx[idx] : agg[idx];
                unsigned pmask = __ballot_sync(0xffffffffu, f == 2);
                if (pmask) {
                    int k = __ffs(pmask) - 1;
                    int contrib = (lane <= k) ? vv : 0;
                    #pragma unroll
                    for (int o = 16; o; o >>= 1)
                        contrib += __shfl_xor_sync(0xffffffffu, contrib, o);
                    excl += contrib;
                    break;
                } else {
                    int contrib = vv;
                    #pragma unroll
                    for (int o = 16; o; o >>= 1)
                        contrib += __shfl_xor_sync(0xffffffffu, contrib, o);
                    excl += contrib;
                    pos -= 32;
                }
            }
            if (lane == 0) {
                s_excl = excl;
                pfx_[b] = excl + total;
                __threadfence();
                flag_[b] = 2;
            }
        }
    }
    __syncthreads();

    if (i < n4) {
        int off = s_excl + wsum[w] + (incl - s);
        int o0 = off, o1 = off + v.x, o2 = o1 + v.y, o3 = o2 + v.z;
        start[4 * i] = o0; start[4 * i + 1] = o1; start[4 * i + 2] = o2; start[4 * i + 3] = o3;
        cursor[4 * i] = o0; cursor[4 * i + 1] = o1; cursor[4 * i + 2] = o2; cursor[4 * i + 3] = o3;
    }
}

__global__ void scatter3_kernel(const int* __restrict__ e0, const int* __restrict__ e1,
                                const int* __restrict__ e2, int e,
                                int* __restrict__ cursor, int* __restrict__ col)
{
    int v = blockIdx.y;
    const int* ei = (v == 0) ? e0 : (v == 1) ? e1 : e2;
    int i = blockIdx.x * blockDim.x + threadIdx.x;
    if (i < e) {
        int d = ei[e + i];
        int p = atomicAdd(&cursor[v * NMAX + d], 1);
        col[p] = ei[i];
    }
}

// ---------------- GAT aggregation: int8 rows, 8-wide batching (warp per destination) ----------------
__global__ void gat_aggregate_kernel(
    const unsigned* __restrict__ xq, const float2* __restrict__ combo, const float* __restrict__ adst,
    const int* __restrict__ start, const int* __restrict__ cnt, const int* __restrict__ col,
    const float* __restrict__ bias, const float* __restrict__ gate_W, const float* __restrict__ gate_b,
    __half* __restrict__ hv, float* __restrict__ eg, int n)
{
    int d = (blockIdx.x * blockDim.x + threadIdx.x) >> 5;
    int lane = threadIdx.x & 31;
    if (d >= n) return;
    int h = lane >> 3;   // head == scale group (channels lane*4..lane*4+3)

    float ad = adst[d * 4 + h];

    // self loop
    float2 cs = combo[d * 4 + h];
    float l = cs.x + ad; l = (l > 0.f) ? l : 0.2f * l;
    float wv = __expf(l);
    float denom = wv;
    float ws = wv * cs.y;
    unsigned su = xq[(size_t)d * 32 + lane];
    float a0 = ws * sb0(su);
    float a1 = ws * sb1(su);
    float a2 = ws * sb2(su);
    float a3 = ws * sb3(su);

    int s0 = start[d];
    int c = cnt[d];

    int e = 0;
    for (; e + 8 <= c; e += 8) {
        int s_[8];
        #pragma unroll
        for (int j = 0; j < 8; j++) s_[j] = __ldcs(&col[s0 + e + j]);
        float2 c_[8];
        unsigned u_[8];
        #pragma unroll
        for (int j = 0; j < 8; j++) {
            c_[j] = combo[s_[j] * 4 + h];
            u_[j] = xq[(size_t)s_[j] * 32 + lane];
        }
        #pragma unroll
        for (int j = 0; j < 8; j++) {
            float lg = c_[j].x + ad; lg = (lg > 0.f) ? lg : 0.2f * lg;
            float we = __expf(lg);
            denom += we;
            float wsj = we * c_[j].y;
            a0 += wsj * sb0(u_[j]);
            a1 += wsj * sb1(u_[j]);
            a2 += wsj * sb2(u_[j]);
            a3 += wsj * sb3(u_[j]);
        }
    }
    for (; e < c; e++) {
        int s = __ldcs(&col[s0 + e]);
        float2 cc = combo[s * 4 + h];
        unsigned u = xq[(size_t)s * 32 + lane];
        float lg = cc.x + ad; lg = (lg > 0.f) ? lg : 0.2f * lg;
        float we = __expf(lg);
        denom += we;
        float wsj = we * cc.y;
        a0 += wsj * sb0(u);
        a1 += wsj * sb1(u);
        a2 += wsj * sb2(u);
        a3 += wsj * sb3(u);
    }

    float inv = 1.f / denom;
    float4 b4 = ((const float4*)bias)[lane];   // channels lane*4..+3
    float o0 = a0 * inv + b4.x;
    float o1 = a1 * inv + b4.y;
    float o2 = a2 * inv + b4.z;
    float o3 = a3 * inv + b4.w;
    o0 = (o0 > 0.f) ? o0 : (__expf(o0) - 1.f);
    o1 = (o1 > 0.f) ? o1 : (__expf(o1) - 1.f);
    o2 = (o2 > 0.f) ? o2 : (__expf(o2) - 1.f);
    o3 = (o3 > 0.f) ? o3 : (__expf(o3) - 1.f);

    __half2 ho0 = __floats2half2_rn(o0, o1);
    __half2 ho1 = __floats2half2_rn(o2, o3);
    unsigned r0 = *(const unsigned*)&ho0;
    unsigned r1 = *(const unsigned*)&ho1;
    asm volatile("st.global.cs.v2.u32 [%0], {%1, %2};"
                 :: "l"(hv + (size_t)d * 128 + lane * 4), "r"(r0), "r"(r1) : "memory");

    float4 g4 = ((const float4*)gate_W)[lane];
    float p = o0 * g4.x + o1 * g4.y + o2 * g4.z + o3 * g4.w;
    #pragma unroll
    for (int off = 16; off; off >>= 1) p += __shfl_xor_sync(0xffffffffu, p, off);
    if (lane == 0) eg[d] = __expf(p + gate_b[0]);
}

// ---------------- graph boundaries ----------------
__global__ void bounds_kernel(const int* __restrict__ batch, int n, int nb,
                              int* __restrict__ gs, int* __restrict__ ge)
{
    int b = blockIdx.x * blockDim.x + threadIdx.x;
    if (b >= nb) return;
    int lo = 0, hi = n;
    while (lo < hi) { int mid = (lo + hi) >> 1; if (batch[mid] < b) lo = mid + 1; else hi = mid; }
    gs[b] = lo;
    lo = 0; hi = n;
    while (lo < hi) { int mid = (lo + hi) >> 1; if (batch[mid] < b + 1) lo = mid + 1; else hi = mid; }
    ge[b] = lo;
}

// ---------------- pooling: 8-wide MLP batching ----------------
__global__ void __launch_bounds__(128) pool3_kernel(
    const __half* __restrict__ hv, const float* __restrict__ eg,
    const int* __restrict__ gs, const int* __restrict__ ge,
    float* __restrict__ combined)
{
    int b = blockIdx.x, v = blockIdx.y, t = threadIdx.x;
    const __half* hv_v = hv + (size_t)v * XH_STRIDE;
    const float* eg_v = eg + v * NMAX;
    int s = gs[b], e2 = ge[b];
    float denom = 0.f, acc = 0.f;
    int i = s;
    for (; i + 8 <= e2; i += 8) {
        float w_[8];
        __half h_[8];
        #pragma unroll
        for (int j = 0; j < 8; j++) w_[j] = eg_v[i + j];
        #pragma unroll
        for (int j = 0; j < 8; j++) h_[j] = hv_v[(size_t)(i + j) * 128 + t];
        #pragma unroll
        for (int j = 0; j < 8; j++) {
            denom += w_[j];
            acc += w_[j] * __half2float(h_[j]);
        }
    }
    for (; i < e2; i++) {
        float w = eg_v[i];
        denom += w;
        acc += w * __half2float(hv_v[(size_t)i * 128 + t]);
    }
    combined[(size_t)b * 384 + v * 128 + t] = (e2 > s) ? (acc / denom) : 0.f;
}

// ---------------- classifier ----------------
__global__ void __launch_bounds__(128) classifier_kernel(
    const float* __restrict__ comb, const float* __restrict__ W1, const float* __restrict__ b1,
    const float* __restrict__ W2, const float* __restrict__ b2, float* __restrict__ out)
{
    __shared__ float cs[384];
    __shared__ float red[4];
    int b = blockIdx.x, t = threadIdx.x;
    for (int i = t; i < 384; i += 128) cs[i] = comb[(size_t)b * 384 + i];
    __syncthreads();
    float acc = b1[t];
    for (int k = 0; k < 384; k++) acc += cs[k] * W1[k * 128 + t];
    acc = (acc > 0.f) ? acc : 0.01f * acc;
    float v = acc * W2[t];
    #pragma unroll
    for (int o = 16; o; o >>= 1) v += __shfl_xor_sync(0xffffffffu, v, o);
    if ((t & 31) == 0) red[t >> 5] = v;
    __syncthreads();
    if (t == 0) out[b] = red[0] + red[1] + red[2] + red[3] + b2[0];
}

// ---------------- launch ----------------
template <typename T>
static T* sym_addr(const void* sym) {
    void* p = nullptr;
    cudaGetSymbolAddress(&p, sym);
    return (T*)p;
}

extern "C" void kernel_launch(void* const* d_in, const int* in_sizes, int n_in,
                              void* d_out, int out_size)
{
    const float* x      = (const float*)d_in[0];
    const int*   e0     = (const int*)d_in[1];
    const int*   e1     = (const int*)d_in[2];
    const int*   e2     = (const int*)d_in[3];
    const int*   batch  = (const int*)d_in[4];
    const float* ln_g   = (const float*)d_in[5];
    const float* ln_b   = (const float*)d_in[6];
    const float* proj_W = (const float*)d_in[7];
    const float* proj_b = (const float*)d_in[8];
    const float* Wv[3]    = {(const float*)d_in[9],  (const float*)d_in[13], (const float*)d_in[17]};
    const float* asv[3]   = {(const float*)d_in[10], (const float*)d_in[14], (const float*)d_in[18]};
    const float* adv[3]   = {(const float*)d_in[11], (const float*)d_in[15], (const float*)d_in[19]};
    const float* biasv[3] = {(const float*)d_in[12], (const float*)d_in[16], (const float*)d_in[20]};
    const float* gate_W = (const float*)d_in[21];
    const float* gate_b = (const float*)d_in[22];
    const float* clf_W1 = (const float*)d_in[23];
    const float* clf_b1 = (const float*)d_in[24];
    const float* clf_W2 = (const float*)d_in[25];
    const float* clf_b2 = (const float*)d_in[26];
    float* out = (float*)d_out;

    int n  = in_sizes[0] / 128;
    int e  = in_sizes[1] / 2;
    int nb = out_size;

    __half* xh   = sym_addr<__half>(g_xh);
    __half* hv   = sym_addr<__half>(g_hv);
    unsigned* xq = sym_addr<unsigned>(g_xq);
    float2* combo= sym_addr<float2>(g_combo);
    float* asrc  = sym_addr<float>(g_asrc);
    float* adst  = sym_addr<float>(g_adst);
    float* eg    = sym_addr<float>(g_eg);
    int*   cnt   = sym_addr<int>(g_cnt);
    int*   strt  = sym_addr<int>(g_start);
    int*   curs  = sym_addr<int>(g_cursor);
    int*   col   = sym_addr<int>(g_col);
    int*   gs    = sym_addr<int>(g_gs);
    int*   ge    = sym_addr<int>(g_ge);
    float* comb  = sym_addr<float>(g_combined);
    unsigned* Wfrag = sym_addr<unsigned>(g_Wfrag16);
    float* attc  = sym_addr<float>(g_attc);
    int*   sflag = sym_addr<int>(g_scan_flag);
    int*   sagg  = sym_addr<int>(g_scan_agg);
    int*   spfx  = sym_addr<int>(g_scan_pfx);

    int node_tiles  = (n + 63) / 64;
    int warp_blocks = (n + 7) / 8;
    int edge_blocks = (e + 255) / 256;

    const int T  = 3 * NMAX;
    const int n4 = T / 4;
    const int sblocks = (n4 + 255) / 256;

    zero_kernel<<<(T + 255) / 256, 256>>>(cnt, T, sflag, 512);
    prep_kernel<<<(32768 + 768 + 255) / 256, 256>>>(
        proj_W, Wv[0], Wv[1], Wv[2],
        asv[0], adv[0], asv[1], adv[1], asv[2], adv[2], Wfrag, attc);
    bounds_kernel<<<(nb + 255) / 256, 256>>>(batch, n, nb, gs, ge);

    fused_front_kernel<<<node_tiles, 256>>>(x, ln_g, ln_b, Wfrag, proj_b, attc,
                                            xh, asrc, adst, n);

    hist3_kernel<<<dim3(edge_blocks, 3), 256>>>(e0, e1, e2, e, cnt);
    quant3_kernel<<<dim3(warp_blocks, 3), 256>>>(xh, asrc, xq, combo, n);
    scan_lookback_kernel<<<sblocks, 256>>>((const int4*)cnt, n4, strt, curs,
                                           sflag, sagg, spfx);
    scatter3_kernel<<<dim3(edge_blocks, 3), 256>>>(e0, e1, e2, e, curs, col);

    // sequential per-view aggregation (start[] holds GLOBAL col offsets; col UNOFFSET)
    for (int v = 0; v < 3; v++) {
        gat_aggregate_kernel<<<warp_blocks, 256>>>(
            xq + (size_t)v * NMAX * 32, combo + v * NMAX * 4, adst + v * NMAX * 4,
            strt + v * NMAX, cnt + v * NMAX, col,
            biasv[v], gate_W, gate_b,
            hv + (size_t)v * XH_STRIDE, eg + v * NMAX, n);
    }

    pool3_kernel<<<dim3(nb, 3), 128>>>(hv, eg, gs, ge, comb);
    classifier_kernel<<<nb, 128>>>(comb, clf_W1, clf_b1, clf_W2, clf_b2, out);
}

// round 14
// speedup vs baseline: 1.1490x; 1.1490x over previous
#include <cuda_runtime.h>
#include <cuda_fp16.h>
#include <cstdint>

#define NMAX 100000
#define EMAX 1600000
#define BMAX 512
#define ROWH 136                     // fp16 tile row stride (halves)
static const size_t XH_STRIDE = (size_t)NMAX * 128;

// ---------------- device scratch ----------------
__device__ __half g_xh[(size_t)3 * NMAX * 128];
__device__ __half g_hv[(size_t)3 * NMAX * 128];
__device__ float g_asrc[3 * NMAX * 4];
__device__ float g_adst[3 * NMAX * 4];
__device__ float g_eg[3 * NMAX];
__device__ int   g_cnt[3 * NMAX];
__device__ int   g_start[3 * NMAX];
__device__ int   g_cursor[3 * NMAX];
__device__ int   g_col[3 * EMAX];
__device__ int   g_gs[BMAX];
__device__ int   g_ge[BMAX];
__device__ float g_combined[(size_t)BMAX * 384];
__device__ unsigned g_Wfrag16[4 * 8192];
__device__ float g_attc[3 * 2 * 128];
// lookback scan state (zeroed each replay)
__device__ int g_scan_flag[512];
__device__ int g_scan_agg[512];
__device__ int g_scan_pfx[512];

// ---------------- mma helpers ----------------
__device__ __forceinline__ void mma_f16(float* d, const unsigned* a, const unsigned* b) {
    asm volatile(
        "mma.sync.aligned.m16n8k16.row.col.f32.f16.f16.f32 "
        "{%0,%1,%2,%3},{%4,%5,%6,%7},{%8,%9},{%0,%1,%2,%3};"
        : "+f"(d[0]), "+f"(d[1]), "+f"(d[2]), "+f"(d[3])
        : "r"(a[0]), "r"(a[1]), "r"(a[2]), "r"(a[3]), "r"(b[0]), "r"(b[1]));
}

__device__ __forceinline__ void ldsm_x4(unsigned* a, uint32_t addr) {
    asm volatile("ldmatrix.sync.aligned.m8n8.x4.shared.b16 {%0,%1,%2,%3}, [%4];"
                 : "=r"(a[0]), "=r"(a[1]), "=r"(a[2]), "=r"(a[3]) : "r"(addr));
}

// ---------------- prep: fp16 fragment-reorder weights, pack att vecs ----------------
__global__ void prep_kernel(
    const float* __restrict__ pw,
    const float* __restrict__ w0, const float* __restrict__ w1, const float* __restrict__ w2,
    const float* __restrict__ as0, const float* __restrict__ ad0,
    const float* __restrict__ as1, const float* __restrict__ ad1,
    const float* __restrict__ as2, const float* __restrict__ ad2,
    unsigned* __restrict__ Wfrag, float* __restrict__ attc)
{
    int i = blockIdx.x * blockDim.x + threadIdx.x;
    if (i < 32768) {
        int breg = i & 1;
        int lane = (i >> 1) & 31;
        int ntg  = (i >> 6) & 15;
        int kt   = (i >> 10) & 7;
        int m    = i >> 13;
        int t = lane & 3, nr = lane >> 2;
        int n = ntg * 8 + nr;
        int k = kt * 16 + 2 * t + breg * 8;
        const float* Wm = (m == 0) ? pw : (m == 1) ? w0 : (m == 2) ? w1 : w2;
        __half lo = __float2half(Wm[k * 128 + n]);
        __half hi = __float2half(Wm[(k + 1) * 128 + n]);
        __half2 h2 = __halves2half2(lo, hi);
        Wfrag[i] = *(unsigned*)&h2;
    } else if (i < 32768 + 768) {
        int j = i - 32768;
        int v = j >> 8;
        int rem = j & 255;
        int sd = rem >> 7;
        int c = rem & 127;
        const float* p;
        if (v == 0) p = sd ? ad0 : as0;
        else if (v == 1) p = sd ? ad1 : as1;
        else p = sd ? ad2 : as2;
        attc[j] = p[c];
    }
}

// ---------------- fused front: LN + proj + 3 view GEMMs + att coefs ----------------
__global__ void __launch_bounds__(256, 4) fused_front_kernel(
    const float* __restrict__ x, const float* __restrict__ ln_g, const float* __restrict__ ln_b,
    const unsigned* __restrict__ Wfrag, const float* __restrict__ proj_b,
    const float* __restrict__ attc,
    __half* __restrict__ xh, float* __restrict__ asrc, float* __restrict__ adst, int n)
{
    __shared__ __align__(16) __half sH[64 * ROWH];
    int t = threadIdx.x;
    int lane = t & 31, w = t >> 5;
    int wr = w >> 2, wc = w & 3;
    int base = blockIdx.x * 64;

    // LN: warp w owns local nodes w*8..w*8+7; lane reads float4 at column lane*4
    {
        float4 lng = *(const float4*)(ln_g + lane * 4);
        float4 lnb = *(const float4*)(ln_b + lane * 4);
        #pragma unroll
        for (int jj = 0; jj < 8; jj++) {
            int j = w * 8 + jj;
            int node = base + j;
            float4 v = make_float4(0.f, 0.f, 0.f, 0.f);
            if (node < n) v = *(const float4*)(x + (size_t)node * 128 + lane * 4);
            float s = v.x + v.y + v.z + v.w;
            float q = v.x * v.x + v.y * v.y + v.z * v.z + v.w * v.w;
            #pragma unroll
            for (int o = 16; o; o >>= 1) {
                s += __shfl_xor_sync(0xffffffffu, s, o);
                q += __shfl_xor_sync(0xffffffffu, q, o);
            }
            float mu = s * (1.f / 128.f);
            float var = q * (1.f / 128.f) - mu * mu;
            float inv = rsqrtf(var + 1e-5f);
            float n0 = (v.x - mu) * inv * lng.x + lnb.x;
            float n1 = (v.y - mu) * inv * lng.y + lnb.y;
            float n2 = (v.z - mu) * inv * lng.z + lnb.z;
            float n3 = (v.w - mu) * inv * lng.w + lnb.w;
            __half2 h0 = __floats2half2_rn(n0, n1);
            __half2 h1 = __floats2half2_rn(n2, n3);
            uint2 pk;
            pk.x = *(unsigned*)&h0;
            pk.y = *(unsigned*)&h1;
            *(uint2*)(sH + j * ROWH + lane * 4) = pk;
        }
    }
    __syncthreads();

    uint32_t sH_u = (uint32_t)__cvta_generic_to_shared(sH);
    int g8 = lane >> 3;
    int lrow = (lane & 7) + ((g8 & 1) << 3);
    int koff = (g8 >> 1) << 3;
    uint32_t abase[2];
    abase[0] = sH_u + (uint32_t)(((wr * 32 + lrow) * ROWH + koff) * 2);
    abase[1] = sH_u + (uint32_t)(((wr * 32 + 16 + lrow) * ROWH + koff) * 2);

    float acc[8][4];

    // ---- GEMM 1: proj ----
    {
        #pragma unroll
        for (int i = 0; i < 8; i++) { acc[i][0] = acc[i][1] = acc[i][2] = acc[i][3] = 0.f; }
        const unsigned* WF = Wfrag;
        #pragma unroll
        for (int kt = 0; kt < 8; kt++) {
            unsigned a[2][4];
            ldsm_x4(a[0], abase[0] + kt * 32);
            ldsm_x4(a[1], abase[1] + kt * 32);
            uint2 b[4];
            #pragma unroll
            for (int nt = 0; nt < 4; nt++)
                b[nt] = *(const uint2*)&WF[(kt * 16 + (wc * 4 + nt)) * 64 + lane * 2];
            #pragma unroll
            for (int mt = 0; mt < 2; mt++)
                #pragma unroll
                for (int nt = 0; nt < 4; nt++)
                    mma_f16(acc[mt * 4 + nt], a[mt], (const unsigned*)&b[nt]);
        }
    }
    __syncthreads();

    #pragma unroll
    for (int mt = 0; mt < 2; mt++) {
        #pragma unroll
        for (int nt = 0; nt < 4; nt++) {
            float* c = acc[mt * 4 + nt];
            int r0 = wr * 32 + mt * 16 + (lane >> 2);
            int c0 = wc * 32 + nt * 8 + (lane & 3) * 2;
            float pb0 = proj_b[c0], pb1 = proj_b[c0 + 1];
            float v0 = c[0] + pb0, v1 = c[1] + pb1, v2 = c[2] + pb0, v3 = c[3] + pb1;
            v0 = (v0 > 0.f) ? v0 : 0.01f * v0;
            v1 = (v1 > 0.f) ? v1 : 0.01f * v1;
            v2 = (v2 > 0.f) ? v2 : 0.01f * v2;
            v3 = (v3 > 0.f) ? v3 : 0.01f * v3;
            *(__half2*)(sH + r0 * ROWH + c0) = __floats2half2_rn(v0, v1);
            *(__half2*)(sH + (r0 + 8) * ROWH + c0) = __floats2half2_rn(v2, v3);
        }
    }
    __syncthreads();

    for (int v = 0; v < 3; v++) {
        const unsigned* WF = Wfrag + (v + 1) * 8192;
        #pragma unroll
        for (int i = 0; i < 8; i++) { acc[i][0] = acc[i][1] = acc[i][2] = acc[i][3] = 0.f; }
        #pragma unroll
        for (int kt = 0; kt < 8; kt++) {
            unsigned a[2][4];
            ldsm_x4(a[0], abase[0] + kt * 32);
            ldsm_x4(a[1], abase[1] + kt * 32);
            uint2 b[4];
            #pragma unroll
            for (int nt = 0; nt < 4; nt++)
                b[nt] = *(const uint2*)&WF[(kt * 16 + (wc * 4 + nt)) * 64 + lane * 2];
            #pragma unroll
            for (int mt = 0; mt < 2; mt++)
                #pragma unroll
                for (int nt = 0; nt < 4; nt++)
                    mma_f16(acc[mt * 4 + nt], a[mt], (const unsigned*)&b[nt]);
        }

        const float* attS = attc + v * 256;
        const float* attD = attS + 128;
        __half* xh_v = xh + (size_t)v * XH_STRIDE;
        float ps[4] = {0.f, 0.f, 0.f, 0.f}, pd[4] = {0.f, 0.f, 0.f, 0.f};
        #pragma unroll
        for (int mt = 0; mt < 2; mt++) {
            #pragma unroll
            for (int nt = 0; nt < 4; nt++) {
                float* c = acc[mt * 4 + nt];
                int r0 = wr * 32 + mt * 16 + (lane >> 2);
                int c0 = wc * 32 + nt * 8 + (lane & 3) * 2;
                int node0 = base + r0, node1 = base + r0 + 8;
                if (node0 < n)
                    *(__half2*)(xh_v + (size_t)node0 * 128 + c0) = __floats2half2_rn(c[0], c[1]);
                if (node1 < n)
                    *(__half2*)(xh_v + (size_t)node1 * 128 + c0) = __floats2half2_rn(c[2], c[3]);
                float s0 = attS[c0], s1 = attS[c0 + 1];
                float d0 = attD[c0], d1 = attD[c0 + 1];
                ps[mt * 2 + 0] += c[0] * s0 + c[1] * s1;
                ps[mt * 2 + 1] += c[2] * s0 + c[3] * s1;
                pd[mt * 2 + 0] += c[0] * d0 + c[1] * d1;
                pd[mt * 2 + 1] += c[2] * d0 + c[3] * d1;
            }
        }
        float* asrc_v = asrc + v * NMAX * 4;
        float* adst_v = adst + v * NMAX * 4;
        #pragma unroll
        for (int idx = 0; idx < 4; idx++) {
            float s = ps[idx], d = pd[idx];
            s += __shfl_xor_sync(0xffffffffu, s, 1);
            s += __shfl_xor_sync(0xffffffffu, s, 2);
            d += __shfl_xor_sync(0xffffffffu, d, 1);
            d += __shfl_xor_sync(0xffffffffu, d, 2);
            if ((lane & 3) == 0) {
                int mt = idx >> 1, half = idx & 1;
                int node = base + wr * 32 + mt * 16 + (lane >> 2) + half * 8;
                if (node < n) {
                    asrc_v[node * 4 + wc] = s;
                    adst_v[node * 4 + wc] = d;
                }
            }
        }
    }
}

// ---------------- CSR build ----------------
__global__ void zero_kernel(int4* cnt4, int n4, int4* flags4, int f4) {
    int i = blockIdx.x * blockDim.x + threadIdx.x;
    int4 z = make_int4(0, 0, 0, 0);
    if (i < n4) cnt4[i] = z;
    if (i < f4) flags4[i] = z;
}

// 4 edges per thread via int4
__global__ void hist3_kernel(const int* __restrict__ e0, const int* __restrict__ e1,
                             const int* __restrict__ e2, int e, int* __restrict__ cnt)
{
    int v = blockIdx.y;
    const int* dst = ((v == 0) ? e0 : (v == 1) ? e1 : e2) + e;
    int* cv = cnt + v * NMAX;
    int i = blockIdx.x * blockDim.x + threadIdx.x;
    int base = i * 4;
    if (base + 3 < e && ((e & 3) == 0)) {
        int4 d4 = __ldcs(&((const int4*)dst)[i]);
        atomicAdd(&cv[d4.x], 1);
        atomicAdd(&cv[d4.y], 1);
        atomicAdd(&cv[d4.z], 1);
        atomicAdd(&cv[d4.w], 1);
    } else {
        for (int k = base; k < e && k < base + 4; k++) atomicAdd(&cv[dst[k]], 1);
    }
}

// ---------------- single-kernel decoupled-lookback scan ----------------
__global__ void __launch_bounds__(256) scan_lookback_kernel(
    const int4* __restrict__ c4, int n4,
    int* __restrict__ start, int* __restrict__ cursor,
    int* flag_, int* agg_, int* pfx_)
{
    volatile int* flag = (volatile int*)flag_;
    volatile int* agg  = (volatile int*)agg_;
    volatile int* pfx  = (volatile int*)pfx_;
    __shared__ int wsum[8];
    __shared__ int s_total;
    __shared__ int s_excl;

    int b = blockIdx.x;
    int t = threadIdx.x, lane = t & 31, w = t >> 5;
    int i = b * 256 + t;
    int4 v = make_int4(0, 0, 0, 0);
    if (i < n4) v = c4[i];
    int s = v.x + v.y + v.z + v.w;
    int incl = s;
    #pragma unroll
    for (int o = 1; o < 32; o <<= 1) {
        int u = __shfl_up_sync(0xffffffffu, incl, o);
        if (lane >= o) incl += u;
    }
    if (lane == 31) wsum[w] = incl;
    if (t == 0) s_excl = 0;
    __syncthreads();
    if (w == 0 && lane < 8) {
        int sv = wsum[lane];
        int si = sv;
        #pragma unroll
        for (int o = 1; o < 8; o <<= 1) {
            int u = __shfl_up_sync(0x000000ffu, si, o);
            if (lane >= o) si += u;
        }
        wsum[lane] = si - sv;
        if (lane == 7) s_total = si;
    }
    __syncthreads();
    int total = s_total;

    if (w == 0) {
        if (b == 0) {
            if (lane == 0) {
                pfx_[0] = total;
                __threadfence();
                flag_[0] = 2;
            }
        } else {
            if (lane == 0) {
                agg_[b] = total;
                __threadfence();
                flag_[b] = 1;
            }
            __syncwarp();
            int excl = 0;
            int pos = b - 1;
            while (true) {
                int idx = pos - lane;
                int f;
                do {
                    f = (idx >= 0) ? flag[idx] : 2;
                } while (!__all_sync(0xffffffffu, f >= 1));
                __threadfence();
                int vv = 0;
                if (idx >= 0) vv = (f == 2) ? pfx[idx] : agg[idx];
                unsigned pmask = __ballot_sync(0xffffffffu, f == 2);
                if (pmask) {
                    int k = __ffs(pmask) - 1;
                    int contrib = (lane <= k) ? vv : 0;
                    #pragma unroll
                    for (int o = 16; o; o >>= 1)
                        contrib += __shfl_xor_sync(0xffffffffu, contrib, o);
                    excl += contrib;
                    break;
                } else {
                    int contrib = vv;
                    #pragma unroll
                    for (int o = 16; o; o >>= 1)
                        contrib += __shfl_xor_sync(0xffffffffu, contrib, o);
                    excl += contrib;
                    pos -= 32;
                }
            }
            if (lane == 0) {
                s_excl = excl;
                pfx_[b] = excl + total;
                __threadfence();
                flag_[b] = 2;
            }
        }
    }
    __syncthreads();

    if (i < n4) {
        int off = s_excl + wsum[w] + (incl - s);
        int o0 = off, o1 = off + v.x, o2 = o1 + v.y, o3 = o2 + v.z;
        start[4 * i] = o0; start[4 * i + 1] = o1; start[4 * i + 2] = o2; start[4 * i + 3] = o3;
        cursor[4 * i] = o0; cursor[4 * i + 1] = o1; cursor[4 * i + 2] = o2; cursor[4 * i + 3] = o3;
    }
}

// 4 edges per thread via int4 (src + dst)
__global__ void scatter3_kernel(const int* __restrict__ e0, const int* __restrict__ e1,
                                const int* __restrict__ e2, int e,
                                int* __restrict__ cursor, int* __restrict__ col)
{
    int v = blockIdx.y;
    const int* ei = (v == 0) ? e0 : (v == 1) ? e1 : e2;
    int* cv = cursor + v * NMAX;
    int i = blockIdx.x * blockDim.x + threadIdx.x;
    int base = i * 4;
    if (base + 3 < e && ((e & 3) == 0)) {
        int4 s4 = __ldcs(&((const int4*)ei)[i]);
        int4 d4 = __ldcs(&((const int4*)(ei + e))[i]);
        int p0 = atomicAdd(&cv[d4.x], 1);
        int p1 = atomicAdd(&cv[d4.y], 1);
        int p2 = atomicAdd(&cv[d4.z], 1);
        int p3 = atomicAdd(&cv[d4.w], 1);
        col[p0] = s4.x;
        col[p1] = s4.y;
        col[p2] = s4.z;
        col[p3] = s4.w;
    } else {
        for (int k = base; k < e && k < base + 4; k++) {
            int d = ei[e + k];
            int p = atomicAdd(&cv[d], 1);
            col[p] = ei[k];
        }
    }
}

// ---------------- GAT aggregation (R10: fp16, 8-wide, warp per destination) ----------------
__global__ void gat_aggregate_kernel(
    const __half* __restrict__ xh, const float* __restrict__ asrc, const float* __restrict__ adst,
    const int* __restrict__ start, const int* __restrict__ cnt, const int* __restrict__ col,
    const float* __restrict__ bias, const float* __restrict__ gate_W, const float* __restrict__ gate_b,
    __half* __restrict__ hv, float* __restrict__ eg, int n)
{
    int d = (blockIdx.x * blockDim.x + threadIdx.x) >> 5;
    int lane = threadIdx.x & 31;
    if (d >= n) return;
    int h = lane >> 3;
    const uint2* xh2 = (const uint2*)xh;

    float ad = adst[d * 4 + h];
    float as = asrc[d * 4 + h];
    float l = as + ad; l = (l > 0.f) ? l : 0.2f * l;
    float wv = __expf(l);
    float denom = wv;
    uint2 selfr = xh2[(size_t)d * 32 + lane];
    float2 sf0 = __half22float2(*(const __half2*)&selfr.x);
    float2 sf1 = __half22float2(*(const __half2*)&selfr.y);
    float4 acc = make_float4(wv * sf0.x, wv * sf0.y, wv * sf1.x, wv * sf1.y);

    int s0 = start[d];
    int c = cnt[d];

    int e = 0;
    for (; e + 8 <= c; e += 8) {
        int s_[8];
        #pragma unroll
        for (int j = 0; j < 8; j++) s_[j] = __ldcs(&col[s0 + e + j]);
        float a_[8];
        uint2 u_[8];
        #pragma unroll
        for (int j = 0; j < 8; j++) {
            a_[j] = asrc[s_[j] * 4 + h];
            u_[j] = xh2[(size_t)s_[j] * 32 + lane];
        }
        #pragma unroll
        for (int j = 0; j < 8; j++) {
            float lg = a_[j] + ad; lg = (lg > 0.f) ? lg : 0.2f * lg;
            float we = __expf(lg);
            denom += we;
            float2 f0 = __half22float2(*(const __half2*)&u_[j].x);
            float2 f1 = __half22float2(*(const __half2*)&u_[j].y);
            acc.x += we * f0.x; acc.y += we * f0.y;
            acc.z += we * f1.x; acc.w += we * f1.y;
        }
    }
    for (; e < c; e++) {
        int s = __ldcs(&col[s0 + e]);
        float a = asrc[s * 4 + h];
        uint2 u = xh2[(size_t)s * 32 + lane];
        float lg = a + ad; lg = (lg > 0.f) ? lg : 0.2f * lg;
        float we = __expf(lg);
        denom += we;
        float2 f0 = __half22float2(*(const __half2*)&u.x);
        float2 f1 = __half22float2(*(const __half2*)&u.y);
        acc.x += we * f0.x; acc.y += we * f0.y;
        acc.z += we * f1.x; acc.w += we * f1.y;
    }

    float inv = 1.f / denom;
    float4 b4 = ((const float4*)bias)[lane];
    float4 o;
    o.x = acc.x * inv + b4.x;
    o.y = acc.y * inv + b4.y;
    o.z = acc.z * inv + b4.z;
    o.w = acc.w * inv + b4.w;
    o.x = (o.x > 0.f) ? o.x : (__expf(o.x) - 1.f);
    o.y = (o.y > 0.f) ? o.y : (__expf(o.y) - 1.f);
    o.z = (o.z > 0.f) ? o.z : (__expf(o.z) - 1.f);
    o.w = (o.w > 0.f) ? o.w : (__expf(o.w) - 1.f);
    __half2 ho0 = __floats2half2_rn(o.x, o.y);
    __half2 ho1 = __floats2half2_rn(o.z, o.w);
    unsigned w0 = *(const unsigned*)&ho0;
    unsigned w1 = *(const unsigned*)&ho1;
    asm volatile("st.global.cs.v2.u32 [%0], {%1, %2};"
                 :: "l"(hv + (size_t)d * 128 + lane * 4), "r"(w0), "r"(w1) : "memory");

    float4 g4 = ((const float4*)gate_W)[lane];
    float p = o.x * g4.x + o.y * g4.y + o.z * g4.z + o.w * g4.w;
    #pragma unroll
    for (int off = 16; off; off >>= 1) p += __shfl_xor_sync(0xffffffffu, p, off);
    if (lane == 0) eg[d] = __expf(p + gate_b[0]);
}

// ---------------- graph boundaries ----------------
__global__ void bounds_kernel(const int* __restrict__ batch, int n, int nb,
                              int* __restrict__ gs, int* __restrict__ ge)
{
    int b = blockIdx.x * blockDim.x + threadIdx.x;
    if (b >= nb) return;
    int lo = 0, hi = n;
    while (lo < hi) { int mid = (lo + hi) >> 1; if (batch[mid] < b) lo = mid + 1; else hi = mid; }
    gs[b] = lo;
    lo = 0; hi = n;
    while (lo < hi) { int mid = (lo + hi) >> 1; if (batch[mid] < b + 1) lo = mid + 1; else hi = mid; }
    ge[b] = lo;
}

// ---------------- pooling: 8-wide MLP batching ----------------
__global__ void __launch_bounds__(128) pool3_kernel(
    const __half* __restrict__ hv, const float* __restrict__ eg,
    const int* __restrict__ gs, const int* __restrict__ ge,
    float* __restrict__ combined)
{
    int b = blockIdx.x, v = blockIdx.y, t = threadIdx.x;
    const __half* hv_v = hv + (size_t)v * XH_STRIDE;
    const float* eg_v = eg + v * NMAX;
    int s = gs[b], e2 = ge[b];
    float denom = 0.f, acc = 0.f;
    int i = s;
    for (; i + 8 <= e2; i += 8) {
        float w_[8];
        __half h_[8];
        #pragma unroll
        for (int j = 0; j < 8; j++) w_[j] = eg_v[i + j];
        #pragma unroll
        for (int j = 0; j < 8; j++) h_[j] = hv_v[(size_t)(i + j) * 128 + t];
        #pragma unroll
        for (int j = 0; j < 8; j++) {
            denom += w_[j];
            acc += w_[j] * __half2float(h_[j]);
        }
    }
    for (; i < e2; i++) {
        float w = eg_v[i];
        denom += w;
        acc += w * __half2float(hv_v[(size_t)i * 128 + t]);
    }
    combined[(size_t)b * 384 + v * 128 + t] = (e2 > s) ? (acc / denom) : 0.f;
}

// ---------------- classifier ----------------
__global__ void __launch_bounds__(128) classifier_kernel(
    const float* __restrict__ comb, const float* __restrict__ W1, const float* __restrict__ b1,
    const float* __restrict__ W2, const float* __restrict__ b2, float* __restrict__ out)
{
    __shared__ float cs[384];
    __shared__ float red[4];
    int b = blockIdx.x, t = threadIdx.x;
    for (int i = t; i < 384; i += 128) cs[i] = comb[(size_t)b * 384 + i];
    __syncthreads();
    float acc = b1[t];
    for (int k = 0; k < 384; k++) acc += cs[k] * W1[k * 128 + t];
    acc = (acc > 0.f) ? acc : 0.01f * acc;
    float v = acc * W2[t];
    #pragma unroll
    for (int o = 16; o; o >>= 1) v += __shfl_xor_sync(0xffffffffu, v, o);
    if ((t & 31) == 0) red[t >> 5] = v;
    __syncthreads();
    if (t == 0) out[b] = red[0] + red[1] + red[2] + red[3] + b2[0];
}

// ---------------- launch ----------------
template <typename T>
static T* sym_addr(const void* sym) {
    void* p = nullptr;
    cudaGetSymbolAddress(&p, sym);
    return (T*)p;
}

extern "C" void kernel_launch(void* const* d_in, const int* in_sizes, int n_in,
                              void* d_out, int out_size)
{
    const float* x      = (const float*)d_in[0];
    const int*   e0     = (const int*)d_in[1];
    const int*   e1     = (const int*)d_in[2];
    const int*   e2     = (const int*)d_in[3];
    const int*   batch  = (const int*)d_in[4];
    const float* ln_g   = (const float*)d_in[5];
    const float* ln_b   = (const float*)d_in[6];
    const float* proj_W = (const float*)d_in[7];
    const float* proj_b = (const float*)d_in[8];
    const float* Wv[3]    = {(const float*)d_in[9],  (const float*)d_in[13], (const float*)d_in[17]};
    const float* asv[3]   = {(const float*)d_in[10], (const float*)d_in[14], (const float*)d_in[18]};
    const float* adv[3]   = {(const float*)d_in[11], (const float*)d_in[15], (const float*)d_in[19]};
    const float* biasv[3] = {(const float*)d_in[12], (const float*)d_in[16], (const float*)d_in[20]};
    const float* gate_W = (const float*)d_in[21];
    const float* gate_b = (const float*)d_in[22];
    const float* clf_W1 = (const float*)d_in[23];
    const float* clf_b1 = (const float*)d_in[24];
    const float* clf_W2 = (const float*)d_in[25];
    const float* clf_b2 = (const float*)d_in[26];
    float* out = (float*)d_out;

    int n  = in_sizes[0] / 128;
    int e  = in_sizes[1] / 2;
    int nb = out_size;

    __half* xh   = sym_addr<__half>(g_xh);
    __half* hv   = sym_addr<__half>(g_hv);
    float* asrc  = sym_addr<float>(g_asrc);
    float* adst  = sym_addr<float>(g_adst);
    float* eg    = sym_addr<float>(g_eg);
    int*   cnt   = sym_addr<int>(g_cnt);
    int*   strt  = sym_addr<int>(g_start);
    int*   curs  = sym_addr<int>(g_cursor);
    int*   col   = sym_addr<int>(g_col);
    int*   gs    = sym_addr<int>(g_gs);
    int*   ge    = sym_addr<int>(g_ge);
    float* comb  = sym_addr<float>(g_combined);
    unsigned* Wfrag = sym_addr<unsigned>(g_Wfrag16);
    float* attc  = sym_addr<float>(g_attc);
    int*   sflag = sym_addr<int>(g_scan_flag);
    int*   sagg  = sym_addr<int>(g_scan_agg);
    int*   spfx  = sym_addr<int>(g_scan_pfx);

    int node_tiles  = (n + 63) / 64;
    int warp_blocks = (n + 7) / 8;
    int edge4_blocks = ((e + 3) / 4 + 255) / 256;

    const int T  = 3 * NMAX;
    const int n4 = T / 4;
    const int sblocks = (n4 + 255) / 256;

    zero_kernel<<<(n4 + 255) / 256, 256>>>((int4*)cnt, n4, (int4*)sflag, 128);
    prep_kernel<<<(32768 + 768 + 255) / 256, 256>>>(
        proj_W, Wv[0], Wv[1], Wv[2],
        asv[0], adv[0], asv[1], adv[1], asv[2], adv[2], Wfrag, attc);
    bounds_kernel<<<(nb + 255) / 256, 256>>>(batch, n, nb, gs, ge);

    fused_front_kernel<<<node_tiles, 256>>>(x, ln_g, ln_b, Wfrag, proj_b, attc,
                                            xh, asrc, adst, n);

    hist3_kernel<<<dim3(edge4_blocks, 3), 256>>>(e0, e1, e2, e, cnt);
    scan_lookback_kernel<<<sblocks, 256>>>((const int4*)cnt, n4, strt, curs,
                                           sflag, sagg, spfx);
    scatter3_kernel<<<dim3(edge4_blocks, 3), 256>>>(e0, e1, e2, e, curs, col);

    // sequential per-view aggregation (start[] holds GLOBAL col offsets; col UNOFFSET)
    for (int v = 0; v < 3; v++) {
        gat_aggregate_kernel<<<warp_blocks, 256>>>(
            xh + (size_t)v * XH_STRIDE, asrc + v * NMAX * 4, adst + v * NMAX * 4,
            strt + v * NMAX, cnt + v * NMAX, col,
            biasv[v], gate_W, gate_b,
            hv + (size_t)v * XH_STRIDE, eg + v * NMAX, n);
    }

    pool3_kernel<<<dim3(nb, 3), 128>>>(hv, eg, gs, ge, comb);
    classifier_kernel<<<nb, 128>>>(comb, clf_W1, clf_b1, clf_W2, clf_b2, out);
}

// round 15
// speedup vs baseline: 1.1790x; 1.0261x over previous
#include <cuda_runtime.h>
#include <cuda_fp16.h>
#include <cstdint>

#define NMAX 100000
#define EMAX 1600000
#define BMAX 512
#define ROWH 136                     // fp16 tile row stride (halves)
static const size_t XH_STRIDE = (size_t)NMAX * 128;

// ---------------- device scratch ----------------
__device__ __half g_xh[(size_t)3 * NMAX * 128];
__device__ __half g_hv[(size_t)3 * NMAX * 128];
__device__ float g_asrc[3 * NMAX * 4];
__device__ float g_adst[3 * NMAX * 4];
__device__ float g_eg[3 * NMAX];
__device__ int   g_cnt[3 * NMAX];
__device__ int   g_start[3 * NMAX];
__device__ int   g_cursor[3 * NMAX];
__device__ int   g_col[3 * EMAX];
__device__ int   g_gs[BMAX];
__device__ int   g_ge[BMAX];
__device__ float g_combined[(size_t)BMAX * 384];
__device__ unsigned g_Wfrag16[4 * 8192];
__device__ float g_attc[3 * 2 * 128];
// lookback scan state (zeroed each replay)
__device__ int g_scan_flag[512];
__device__ int g_scan_agg[512];
__device__ int g_scan_pfx[512];

// ---------------- mma helpers ----------------
__device__ __forceinline__ void mma_f16(float* d, const unsigned* a, const unsigned* b) {
    asm volatile(
        "mma.sync.aligned.m16n8k16.row.col.f32.f16.f16.f32 "
        "{%0,%1,%2,%3},{%4,%5,%6,%7},{%8,%9},{%0,%1,%2,%3};"
        : "+f"(d[0]), "+f"(d[1]), "+f"(d[2]), "+f"(d[3])
        : "r"(a[0]), "r"(a[1]), "r"(a[2]), "r"(a[3]), "r"(b[0]), "r"(b[1]));
}

__device__ __forceinline__ void ldsm_x4(unsigned* a, uint32_t addr) {
    asm volatile("ldmatrix.sync.aligned.m8n8.x4.shared.b16 {%0,%1,%2,%3}, [%4];"
                 : "=r"(a[0]), "=r"(a[1]), "=r"(a[2]), "=r"(a[3]) : "r"(addr));
}

// ---------------- prep: fp16 fragment-reorder weights, pack att vecs ----------------
__global__ void prep_kernel(
    const float* __restrict__ pw,
    const float* __restrict__ w0, const float* __restrict__ w1, const float* __restrict__ w2,
    const float* __restrict__ as0, const float* __restrict__ ad0,
    const float* __restrict__ as1, const float* __restrict__ ad1,
    const float* __restrict__ as2, const float* __restrict__ ad2,
    unsigned* __restrict__ Wfrag, float* __restrict__ attc)
{
    int i = blockIdx.x * blockDim.x + threadIdx.x;
    if (i < 32768) {
        int breg = i & 1;
        int lane = (i >> 1) & 31;
        int ntg  = (i >> 6) & 15;
        int kt   = (i >> 10) & 7;
        int m    = i >> 13;
        int t = lane & 3, nr = lane >> 2;
        int n = ntg * 8 + nr;
        int k = kt * 16 + 2 * t + breg * 8;
        const float* Wm = (m == 0) ? pw : (m == 1) ? w0 : (m == 2) ? w1 : w2;
        __half lo = __float2half(Wm[k * 128 + n]);
        __half hi = __float2half(Wm[(k + 1) * 128 + n]);
        __half2 h2 = __halves2half2(lo, hi);
        Wfrag[i] = *(unsigned*)&h2;
    } else if (i < 32768 + 768) {
        int j = i - 32768;
        int v = j >> 8;
        int rem = j & 255;
        int sd = rem >> 7;
        int c = rem & 127;
        const float* p;
        if (v == 0) p = sd ? ad0 : as0;
        else if (v == 1) p = sd ? ad1 : as1;
        else p = sd ? ad2 : as2;
        attc[j] = p[c];
    }
}

// ---------------- fused front: LN + proj + 3 view GEMMs + att coefs ----------------
__global__ void __launch_bounds__(256) fused_front_kernel(
    const float* __restrict__ x, const float* __restrict__ ln_g, const float* __restrict__ ln_b,
    const unsigned* __restrict__ Wfrag, const float* __restrict__ proj_b,
    const float* __restrict__ attc,
    __half* __restrict__ xh, float* __restrict__ asrc, float* __restrict__ adst, int n)
{
    __shared__ __align__(16) __half sH[64 * ROWH];
    int t = threadIdx.x;
    int lane = t & 31, w = t >> 5;
    int wr = w >> 2, wc = w & 3;
    int base = blockIdx.x * 64;

    // LN: warp w owns local nodes w*8..w*8+7; lane reads float4 at column lane*4
    {
        float4 lng = *(const float4*)(ln_g + lane * 4);
        float4 lnb = *(const float4*)(ln_b + lane * 4);
        #pragma unroll
        for (int jj = 0; jj < 8; jj++) {
            int j = w * 8 + jj;
            int node = base + j;
            float4 v = make_float4(0.f, 0.f, 0.f, 0.f);
            if (node < n) v = *(const float4*)(x + (size_t)node * 128 + lane * 4);
            float s = v.x + v.y + v.z + v.w;
            float q = v.x * v.x + v.y * v.y + v.z * v.z + v.w * v.w;
            #pragma unroll
            for (int o = 16; o; o >>= 1) {
                s += __shfl_xor_sync(0xffffffffu, s, o);
                q += __shfl_xor_sync(0xffffffffu, q, o);
            }
            float mu = s * (1.f / 128.f);
            float var = q * (1.f / 128.f) - mu * mu;
            float inv = rsqrtf(var + 1e-5f);
            float n0 = (v.x - mu) * inv * lng.x + lnb.x;
            float n1 = (v.y - mu) * inv * lng.y + lnb.y;
            float n2 = (v.z - mu) * inv * lng.z + lnb.z;
            float n3 = (v.w - mu) * inv * lng.w + lnb.w;
            __half2 h0 = __floats2half2_rn(n0, n1);
            __half2 h1 = __floats2half2_rn(n2, n3);
            uint2 pk;
            pk.x = *(unsigned*)&h0;
            pk.y = *(unsigned*)&h1;
            *(uint2*)(sH + j * ROWH + lane * 4) = pk;
        }
    }
    __syncthreads();

    uint32_t sH_u = (uint32_t)__cvta_generic_to_shared(sH);
    int g8 = lane >> 3;
    int lrow = (lane & 7) + ((g8 & 1) << 3);
    int koff = (g8 >> 1) << 3;
    uint32_t abase[2];
    abase[0] = sH_u + (uint32_t)(((wr * 32 + lrow) * ROWH + koff) * 2);
    abase[1] = sH_u + (uint32_t)(((wr * 32 + 16 + lrow) * ROWH + koff) * 2);

    float acc[8][4];

    // ---- GEMM 1: proj ----
    {
        #pragma unroll
        for (int i = 0; i < 8; i++) { acc[i][0] = acc[i][1] = acc[i][2] = acc[i][3] = 0.f; }
        const unsigned* WF = Wfrag;
        #pragma unroll
        for (int kt = 0; kt < 8; kt++) {
            unsigned a[2][4];
            ldsm_x4(a[0], abase[0] + kt * 32);
            ldsm_x4(a[1], abase[1] + kt * 32);
            uint2 b[4];
            #pragma unroll
            for (int nt = 0; nt < 4; nt++)
                b[nt] = *(const uint2*)&WF[(kt * 16 + (wc * 4 + nt)) * 64 + lane * 2];
            #pragma unroll
            for (int mt = 0; mt < 2; mt++)
                #pragma unroll
                for (int nt = 0; nt < 4; nt++)
                    mma_f16(acc[mt * 4 + nt], a[mt], (const unsigned*)&b[nt]);
        }
    }
    __syncthreads();

    #pragma unroll
    for (int mt = 0; mt < 2; mt++) {
        #pragma unroll
        for (int nt = 0; nt < 4; nt++) {
            float* c = acc[mt * 4 + nt];
            int r0 = wr * 32 + mt * 16 + (lane >> 2);
            int c0 = wc * 32 + nt * 8 + (lane & 3) * 2;
            float pb0 = proj_b[c0], pb1 = proj_b[c0 + 1];
            float v0 = c[0] + pb0, v1 = c[1] + pb1, v2 = c[2] + pb0, v3 = c[3] + pb1;
            v0 = (v0 > 0.f) ? v0 : 0.01f * v0;
            v1 = (v1 > 0.f) ? v1 : 0.01f * v1;
            v2 = (v2 > 0.f) ? v2 : 0.01f * v2;
            v3 = (v3 > 0.f) ? v3 : 0.01f * v3;
            *(__half2*)(sH + r0 * ROWH + c0) = __floats2half2_rn(v0, v1);
            *(__half2*)(sH + (r0 + 8) * ROWH + c0) = __floats2half2_rn(v2, v3);
        }
    }
    __syncthreads();

    for (int v = 0; v < 3; v++) {
        const unsigned* WF = Wfrag + (v + 1) * 8192;
        #pragma unroll
        for (int i = 0; i < 8; i++) { acc[i][0] = acc[i][1] = acc[i][2] = acc[i][3] = 0.f; }
        #pragma unroll
        for (int kt = 0; kt < 8; kt++) {
            unsigned a[2][4];
            ldsm_x4(a[0], abase[0] + kt * 32);
            ldsm_x4(a[1], abase[1] + kt * 32);
            uint2 b[4];
            #pragma unroll
            for (int nt = 0; nt < 4; nt++)
                b[nt] = *(const uint2*)&WF[(kt * 16 + (wc * 4 + nt)) * 64 + lane * 2];
            #pragma unroll
            for (int mt = 0; mt < 2; mt++)
                #pragma unroll
                for (int nt = 0; nt < 4; nt++)
                    mma_f16(acc[mt * 4 + nt], a[mt], (const unsigned*)&b[nt]);
        }

        const float* attS = attc + v * 256;
        const float* attD = attS + 128;
        __half* xh_v = xh + (size_t)v * XH_STRIDE;
        float ps[4] = {0.f, 0.f, 0.f, 0.f}, pd[4] = {0.f, 0.f, 0.f, 0.f};
        #pragma unroll
        for (int mt = 0; mt < 2; mt++) {
            #pragma unroll
            for (int nt = 0; nt < 4; nt++) {
                float* c = acc[mt * 4 + nt];
                int r0 = wr * 32 + mt * 16 + (lane >> 2);
                int c0 = wc * 32 + nt * 8 + (lane & 3) * 2;
                int node0 = base + r0, node1 = base + r0 + 8;
                if (node0 < n)
                    *(__half2*)(xh_v + (size_t)node0 * 128 + c0) = __floats2half2_rn(c[0], c[1]);
                if (node1 < n)
                    *(__half2*)(xh_v + (size_t)node1 * 128 + c0) = __floats2half2_rn(c[2], c[3]);
                float s0 = attS[c0], s1 = attS[c0 + 1];
                float d0 = attD[c0], d1 = attD[c0 + 1];
                ps[mt * 2 + 0] += c[0] * s0 + c[1] * s1;
                ps[mt * 2 + 1] += c[2] * s0 + c[3] * s1;
                pd[mt * 2 + 0] += c[0] * d0 + c[1] * d1;
                pd[mt * 2 + 1] += c[2] * d0 + c[3] * d1;
            }
        }
        float* asrc_v = asrc + v * NMAX * 4;
        float* adst_v = adst + v * NMAX * 4;
        #pragma unroll
        for (int idx = 0; idx < 4; idx++) {
            float s = ps[idx], d = pd[idx];
            s += __shfl_xor_sync(0xffffffffu, s, 1);
            s += __shfl_xor_sync(0xffffffffu, s, 2);
            d += __shfl_xor_sync(0xffffffffu, d, 1);
            d += __shfl_xor_sync(0xffffffffu, d, 2);
            if ((lane & 3) == 0) {
                int mt = idx >> 1, half = idx & 1;
                int node = base + wr * 32 + mt * 16 + (lane >> 2) + half * 8;
                if (node < n) {
                    asrc_v[node * 4 + wc] = s;
                    adst_v[node * 4 + wc] = d;
                }
            }
        }
    }
}

// ---------------- CSR build ----------------
__global__ void zero_kernel(int4* cnt4, int n4, int4* flags4, int f4) {
    int i = blockIdx.x * blockDim.x + threadIdx.x;
    int4 z = make_int4(0, 0, 0, 0);
    if (i < n4) cnt4[i] = z;
    if (i < f4) flags4[i] = z;
}

// 4 edges per thread via int4
__global__ void hist3_kernel(const int* __restrict__ e0, const int* __restrict__ e1,
                             const int* __restrict__ e2, int e, int* __restrict__ cnt)
{
    int v = blockIdx.y;
    const int* dst = ((v == 0) ? e0 : (v == 1) ? e1 : e2) + e;
    int* cv = cnt + v * NMAX;
    int i = blockIdx.x * blockDim.x + threadIdx.x;
    int base = i * 4;
    if (base + 3 < e && ((e & 3) == 0)) {
        int4 d4 = __ldcs(&((const int4*)dst)[i]);
        atomicAdd(&cv[d4.x], 1);
        atomicAdd(&cv[d4.y], 1);
        atomicAdd(&cv[d4.z], 1);
        atomicAdd(&cv[d4.w], 1);
    } else {
        for (int k = base; k < e && k < base + 4; k++) atomicAdd(&cv[dst[k]], 1);
    }
}

// ---------------- single-kernel decoupled-lookback scan ----------------
__global__ void __launch_bounds__(256) scan_lookback_kernel(
    const int4* __restrict__ c4, int n4,
    int* __restrict__ start, int* __restrict__ cursor,
    int* flag_, int* agg_, int* pfx_)
{
    volatile int* flag = (volatile int*)flag_;
    volatile int* agg  = (volatile int*)agg_;
    volatile int* pfx  = (volatile int*)pfx_;
    __shared__ int wsum[8];
    __shared__ int s_total;
    __shared__ int s_excl;

    int b = blockIdx.x;
    int t = threadIdx.x, lane = t & 31, w = t >> 5;
    int i = b * 256 + t;
    int4 v = make_int4(0, 0, 0, 0);
    if (i < n4) v = c4[i];
    int s = v.x + v.y + v.z + v.w;
    int incl = s;
    #pragma unroll
    for (int o = 1; o < 32; o <<= 1) {
        int u = __shfl_up_sync(0xffffffffu, incl, o);
        if (lane >= o) incl += u;
    }
    if (lane == 31) wsum[w] = incl;
    if (t == 0) s_excl = 0;
    __syncthreads();
    if (w == 0 && lane < 8) {
        int sv = wsum[lane];
        int si = sv;
        #pragma unroll
        for (int o = 1; o < 8; o <<= 1) {
            int u = __shfl_up_sync(0x000000ffu, si, o);
            if (lane >= o) si += u;
        }
        wsum[lane] = si - sv;
        if (lane == 7) s_total = si;
    }
    __syncthreads();
    int total = s_total;

    if (w == 0) {
        if (b == 0) {
            if (lane == 0) {
                pfx_[0] = total;
                __threadfence();
                flag_[0] = 2;
            }
        } else {
            if (lane == 0) {
                agg_[b] = total;
                __threadfence();
                flag_[b] = 1;
            }
            __syncwarp();
            int excl = 0;
            int pos = b - 1;
            while (true) {
                int idx = pos - lane;
                int f;
                do {
                    f = (idx >= 0) ? flag[idx] : 2;
                } while (!__all_sync(0xffffffffu, f >= 1));
                __threadfence();
                int vv = 0;
                if (idx >= 0) vv = (f == 2) ? pfx[idx] : agg[idx];
                unsigned pmask = __ballot_sync(0xffffffffu, f == 2);
                if (pmask) {
                    int k = __ffs(pmask) - 1;
                    int contrib = (lane <= k) ? vv : 0;
                    #pragma unroll
                    for (int o = 16; o; o >>= 1)
                        contrib += __shfl_xor_sync(0xffffffffu, contrib, o);
                    excl += contrib;
                    break;
                } else {
                    int contrib = vv;
                    #pragma unroll
                    for (int o = 16; o; o >>= 1)
                        contrib += __shfl_xor_sync(0xffffffffu, contrib, o);
                    excl += contrib;
                    pos -= 32;
                }
            }
            if (lane == 0) {
                s_excl = excl;
                pfx_[b] = excl + total;
                __threadfence();
                flag_[b] = 2;
            }
        }
    }
    __syncthreads();

    if (i < n4) {
        int off = s_excl + wsum[w] + (incl - s);
        int o0 = off, o1 = off + v.x, o2 = o1 + v.y, o3 = o2 + v.z;
        start[4 * i] = o0; start[4 * i + 1] = o1; start[4 * i + 2] = o2; start[4 * i + 3] = o3;
        cursor[4 * i] = o0; cursor[4 * i + 1] = o1; cursor[4 * i + 2] = o2; cursor[4 * i + 3] = o3;
    }
}

// 4 edges per thread via int4 (src + dst)
__global__ void scatter3_kernel(const int* __restrict__ e0, const int* __restrict__ e1,
                                const int* __restrict__ e2, int e,
                                int* __restrict__ cursor, int* __restrict__ col)
{
    int v = blockIdx.y;
    const int* ei = (v == 0) ? e0 : (v == 1) ? e1 : e2;
    int* cv = cursor + v * NMAX;
    int i = blockIdx.x * blockDim.x + threadIdx.x;
    int base = i * 4;
    if (base + 3 < e && ((e & 3) == 0)) {
        int4 s4 = __ldcs(&((const int4*)ei)[i]);
        int4 d4 = __ldcs(&((const int4*)(ei + e))[i]);
        int p0 = atomicAdd(&cv[d4.x], 1);
        int p1 = atomicAdd(&cv[d4.y], 1);
        int p2 = atomicAdd(&cv[d4.z], 1);
        int p3 = atomicAdd(&cv[d4.w], 1);
        col[p0] = s4.x;
        col[p1] = s4.y;
        col[p2] = s4.z;
        col[p3] = s4.w;
    } else {
        for (int k = base; k < e && k < base + 4; k++) {
            int d = ei[e + k];
            int p = atomicAdd(&cv[d], 1);
            col[p] = ei[k];
        }
    }
}

// ---------------- GAT aggregation (fp16, 8-wide, warp per destination) ----------------
__global__ void gat_aggregate_kernel(
    const __half* __restrict__ xh, const float* __restrict__ asrc, const float* __restrict__ adst,
    const int* __restrict__ start, const int* __restrict__ cnt, const int* __restrict__ col,
    const float* __restrict__ bias, const float* __restrict__ gate_W, const float* __restrict__ gate_b,
    __half* __restrict__ hv, float* __restrict__ eg, int n)
{
    int d = (blockIdx.x * blockDim.x + threadIdx.x) >> 5;
    int lane = threadIdx.x & 31;
    if (d >= n) return;
    int h = lane >> 3;
    const uint2* xh2 = (const uint2*)xh;

    float ad = adst[d * 4 + h];
    float as = asrc[d * 4 + h];
    float l = as + ad; l = (l > 0.f) ? l : 0.2f * l;
    float wv = __expf(l);
    float denom = wv;
    uint2 selfr = xh2[(size_t)d * 32 + lane];
    float2 sf0 = __half22float2(*(const __half2*)&selfr.x);
    float2 sf1 = __half22float2(*(const __half2*)&selfr.y);
    float4 acc = make_float4(wv * sf0.x, wv * sf0.y, wv * sf1.x, wv * sf1.y);

    int s0 = start[d];
    int c = cnt[d];

    int e = 0;
    for (; e + 8 <= c; e += 8) {
        int s_[8];
        #pragma unroll
        for (int j = 0; j < 8; j++) s_[j] = __ldcs(&col[s0 + e + j]);
        float a_[8];
        uint2 u_[8];
        #pragma unroll
        for (int j = 0; j < 8; j++) {
            a_[j] = asrc[s_[j] * 4 + h];
            u_[j] = xh2[(size_t)s_[j] * 32 + lane];
        }
        #pragma unroll
        for (int j = 0; j < 8; j++) {
            float lg = a_[j] + ad; lg = (lg > 0.f) ? lg : 0.2f * lg;
            float we = __expf(lg);
            denom += we;
            float2 f0 = __half22float2(*(const __half2*)&u_[j].x);
            float2 f1 = __half22float2(*(const __half2*)&u_[j].y);
            acc.x += we * f0.x; acc.y += we * f0.y;
            acc.z += we * f1.x; acc.w += we * f1.y;
        }
    }
    for (; e < c; e++) {
        int s = __ldcs(&col[s0 + e]);
        float a = asrc[s * 4 + h];
        uint2 u = xh2[(size_t)s * 32 + lane];
        float lg = a + ad; lg = (lg > 0.f) ? lg : 0.2f * lg;
        float we = __expf(lg);
        denom += we;
        float2 f0 = __half22float2(*(const __half2*)&u.x);
        float2 f1 = __half22float2(*(const __half2*)&u.y);
        acc.x += we * f0.x; acc.y += we * f0.y;
        acc.z += we * f1.x; acc.w += we * f1.y;
    }

    float inv = 1.f / denom;
    float4 b4 = ((const float4*)bias)[lane];
    float4 o;
    o.x = acc.x * inv + b4.x;
    o.y = acc.y * inv + b4.y;
    o.z = acc.z * inv + b4.z;
    o.w = acc.w * inv + b4.w;
    o.x = (o.x > 0.f) ? o.x : (__expf(o.x) - 1.f);
    o.y = (o.y > 0.f) ? o.y : (__expf(o.y) - 1.f);
    o.z = (o.z > 0.f) ? o.z : (__expf(o.z) - 1.f);
    o.w = (o.w > 0.f) ? o.w : (__expf(o.w) - 1.f);
    __half2 ho0 = __floats2half2_rn(o.x, o.y);
    __half2 ho1 = __floats2half2_rn(o.z, o.w);
    unsigned w0 = *(const unsigned*)&ho0;
    unsigned w1 = *(const unsigned*)&ho1;
    asm volatile("st.global.cs.v2.u32 [%0], {%1, %2};"
                 :: "l"(hv + (size_t)d * 128 + lane * 4), "r"(w0), "r"(w1) : "memory");

    float4 g4 = ((const float4*)gate_W)[lane];
    float p = o.x * g4.x + o.y * g4.y + o.z * g4.z + o.w * g4.w;
    #pragma unroll
    for (int off = 16; off; off >>= 1) p += __shfl_xor_sync(0xffffffffu, p, off);
    if (lane == 0) eg[d] = __expf(p + gate_b[0]);
}

// ---------------- graph boundaries ----------------
__global__ void bounds_kernel(const int* __restrict__ batch, int n, int nb,
                              int* __restrict__ gs, int* __restrict__ ge)
{
    int b = blockIdx.x * blockDim.x + threadIdx.x;
    if (b >= nb) return;
    int lo = 0, hi = n;
    while (lo < hi) { int mid = (lo + hi) >> 1; if (batch[mid] < b) lo = mid + 1; else hi = mid; }
    gs[b] = lo;
    lo = 0; hi = n;
    while (lo < hi) { int mid = (lo + hi) >> 1; if (batch[mid] < b + 1) lo = mid + 1; else hi = mid; }
    ge[b] = lo;
}

// ---------------- pooling: 8-wide MLP batching ----------------
__global__ void __launch_bounds__(128) pool3_kernel(
    const __half* __restrict__ hv, const float* __restrict__ eg,
    const int* __restrict__ gs, const int* __restrict__ ge,
    float* __restrict__ combined)
{
    int b = blockIdx.x, v = blockIdx.y, t = threadIdx.x;
    const __half* hv_v = hv + (size_t)v * XH_STRIDE;
    const float* eg_v = eg + v * NMAX;
    int s = gs[b], e2 = ge[b];
    float denom = 0.f, acc = 0.f;
    int i = s;
    for (; i + 8 <= e2; i += 8) {
        float w_[8];
        __half h_[8];
        #pragma unroll
        for (int j = 0; j < 8; j++) w_[j] = eg_v[i + j];
        #pragma unroll
        for (int j = 0; j < 8; j++) h_[j] = hv_v[(size_t)(i + j) * 128 + t];
        #pragma unroll
        for (int j = 0; j < 8; j++) {
            denom += w_[j];
            acc += w_[j] * __half2float(h_[j]);
        }
    }
    for (; i < e2; i++) {
        float w = eg_v[i];
        denom += w;
        acc += w * __half2float(hv_v[(size_t)i * 128 + t]);
    }
    combined[(size_t)b * 384 + v * 128 + t] = (e2 > s) ? (acc / denom) : 0.f;
}

// ---------------- classifier ----------------
__global__ void __launch_bounds__(128) classifier_kernel(
    const float* __restrict__ comb, const float* __restrict__ W1, const float* __restrict__ b1,
    const float* __restrict__ W2, const float* __restrict__ b2, float* __restrict__ out)
{
    __shared__ float cs[384];
    __shared__ float red[4];
    int b = blockIdx.x, t = threadIdx.x;
    for (int i = t; i < 384; i += 128) cs[i] = comb[(size_t)b * 384 + i];
    __syncthreads();
    float acc = b1[t];
    for (int k = 0; k < 384; k++) acc += cs[k] * W1[k * 128 + t];
    acc = (acc > 0.f) ? acc : 0.01f * acc;
    float v = acc * W2[t];
    #pragma unroll
    for (int o = 16; o; o >>= 1) v += __shfl_xor_sync(0xffffffffu, v, o);
    if ((t & 31) == 0) red[t >> 5] = v;
    __syncthreads();
    if (t == 0) out[b] = red[0] + red[1] + red[2] + red[3] + b2[0];
}

// ---------------- launch ----------------
template <typename T>
static T* sym_addr(const void* sym) {
    void* p = nullptr;
    cudaGetSymbolAddress(&p, sym);
    return (T*)p;
}

extern "C" void kernel_launch(void* const* d_in, const int* in_sizes, int n_in,
                              void* d_out, int out_size)
{
    const float* x      = (const float*)d_in[0];
    const int*   e0     = (const int*)d_in[1];
    const int*   e1     = (const int*)d_in[2];
    const int*   e2     = (const int*)d_in[3];
    const int*   batch  = (const int*)d_in[4];
    const float* ln_g   = (const float*)d_in[5];
    const float* ln_b   = (const float*)d_in[6];
    const float* proj_W = (const float*)d_in[7];
    const float* proj_b = (const float*)d_in[8];
    const float* Wv[3]    = {(const float*)d_in[9],  (const float*)d_in[13], (const float*)d_in[17]};
    const float* asv[3]   = {(const float*)d_in[10], (const float*)d_in[14], (const float*)d_in[18]};
    const float* adv[3]   = {(const float*)d_in[11], (const float*)d_in[15], (const float*)d_in[19]};
    const float* biasv[3] = {(const float*)d_in[12], (const float*)d_in[16], (const float*)d_in[20]};
    const float* gate_W = (const float*)d_in[21];
    const float* gate_b = (const float*)d_in[22];
    const float* clf_W1 = (const float*)d_in[23];
    const float* clf_b1 = (const float*)d_in[24];
    const float* clf_W2 = (const float*)d_in[25];
    const float* clf_b2 = (const float*)d_in[26];
    float* out = (float*)d_out;

    int n  = in_sizes[0] / 128;
    int e  = in_sizes[1] / 2;
    int nb = out_size;

    __half* xh   = sym_addr<__half>(g_xh);
    __half* hv   = sym_addr<__half>(g_hv);
    float* asrc  = sym_addr<float>(g_asrc);
    float* adst  = sym_addr<float>(g_adst);
    float* eg    = sym_addr<float>(g_eg);
    int*   cnt   = sym_addr<int>(g_cnt);
    int*   strt  = sym_addr<int>(g_start);
    int*   curs  = sym_addr<int>(g_cursor);
    int*   col   = sym_addr<int>(g_col);
    int*   gs    = sym_addr<int>(g_gs);
    int*   ge    = sym_addr<int>(g_ge);
    float* comb  = sym_addr<float>(g_combined);
    unsigned* Wfrag = sym_addr<unsigned>(g_Wfrag16);
    float* attc  = sym_addr<float>(g_attc);
    int*   sflag = sym_addr<int>(g_scan_flag);
    int*   sagg  = sym_addr<int>(g_scan_agg);
    int*   spfx  = sym_addr<int>(g_scan_pfx);

    int node_tiles  = (n + 63) / 64;
    int warp_blocks = (n + 7) / 8;
    int edge4_blocks = ((e + 3) / 4 + 255) / 256;

    const int T  = 3 * NMAX;
    const int n4 = T / 4;
    const int sblocks = (n4 + 255) / 256;

    zero_kernel<<<(n4 + 255) / 256, 256>>>((int4*)cnt, n4, (int4*)sflag, 128);
    prep_kernel<<<(32768 + 768 + 255) / 256, 256>>>(
        proj_W, Wv[0], Wv[1], Wv[2],
        asv[0], adv[0], asv[1], adv[1], asv[2], adv[2], Wfrag, attc);
    bounds_kernel<<<(nb + 255) / 256, 256>>>(batch, n, nb, gs, ge);

    fused_front_kernel<<<node_tiles, 256>>>(x, ln_g, ln_b, Wfrag, proj_b, attc,
                                            xh, asrc, adst, n);

    hist3_kernel<<<dim3(edge4_blocks, 3), 256>>>(e0, e1, e2, e, cnt);
    scan_lookback_kernel<<<sblocks, 256>>>((const int4*)cnt, n4, strt, curs,
                                           sflag, sagg, spfx);
    scatter3_kernel<<<dim3(edge4_blocks, 3), 256>>>(e0, e1, e2, e, curs, col);

    // sequential per-view aggregation (start[] holds GLOBAL col offsets; col UNOFFSET)
    for (int v = 0; v < 3; v++) {
        gat_aggregate_kernel<<<warp_blocks, 256>>>(
            xh + (size_t)v * XH_STRIDE, asrc + v * NMAX * 4, adst + v * NMAX * 4,
            strt + v * NMAX, cnt + v * NMAX, col,
            biasv[v], gate_W, gate_b,
            hv + (size_t)v * XH_STRIDE, eg + v * NMAX, n);
    }

    pool3_kernel<<<dim3(nb, 3), 128>>>(hv, eg, gs, ge, comb);
    classifier_kernel<<<nb, 128>>>(comb, clf_W1, clf_b1, clf_W2, clf_b2, out);
}

// round 16
// speedup vs baseline: 1.2378x; 1.0499x over previous
#include <cuda_runtime.h>
#include <cuda_fp16.h>
#include <cstdint>

#define NMAX 100000
#define EMAX 1600000
#define BMAX 512
#define ROWH 136                     // fp16 tile row stride (halves)
static const size_t XH_STRIDE = (size_t)NMAX * 128;

// ---------------- device scratch ----------------
__device__ __half g_xh[(size_t)3 * NMAX * 128];
__device__ __half g_hv[(size_t)3 * NMAX * 128];
__device__ float g_asrc[3 * NMAX * 4];
__device__ float g_adst[3 * NMAX * 4];
__device__ float g_eg[3 * NMAX];
__device__ int   g_cnt[3 * NMAX];
__device__ int   g_start[3 * NMAX];
__device__ int   g_cursor[3 * NMAX];
__device__ int   g_col[3 * EMAX];
__device__ int   g_gs[BMAX];
__device__ int   g_ge[BMAX];
__device__ float g_combined[(size_t)BMAX * 384];
__device__ unsigned g_Wfrag16[4 * 8192];
__device__ float g_attc[3 * 2 * 128];
// lookback scan state (zeroed each replay)
__device__ int g_scan_flag[512];
__device__ int g_scan_agg[512];
__device__ int g_scan_pfx[512];

// ---------------- mma helpers ----------------
__device__ __forceinline__ void mma_f16(float* d, const unsigned* a, const unsigned* b) {
    asm volatile(
        "mma.sync.aligned.m16n8k16.row.col.f32.f16.f16.f32 "
        "{%0,%1,%2,%3},{%4,%5,%6,%7},{%8,%9},{%0,%1,%2,%3};"
        : "+f"(d[0]), "+f"(d[1]), "+f"(d[2]), "+f"(d[3])
        : "r"(a[0]), "r"(a[1]), "r"(a[2]), "r"(a[3]), "r"(b[0]), "r"(b[1]));
}

__device__ __forceinline__ void ldsm_x4(unsigned* a, uint32_t addr) {
    asm volatile("ldmatrix.sync.aligned.m8n8.x4.shared.b16 {%0,%1,%2,%3}, [%4];"
                 : "=r"(a[0]), "=r"(a[1]), "=r"(a[2]), "=r"(a[3]) : "r"(addr));
}

// ---------------- prep: fp16 fragment-reorder weights, pack att vecs ----------------
__global__ void prep_kernel(
    const float* __restrict__ pw,
    const float* __restrict__ w0, const float* __restrict__ w1, const float* __restrict__ w2,
    const float* __restrict__ as0, const float* __restrict__ ad0,
    const float* __restrict__ as1, const float* __restrict__ ad1,
    const float* __restrict__ as2, const float* __restrict__ ad2,
    unsigned* __restrict__ Wfrag, float* __restrict__ attc)
{
    int i = blockIdx.x * blockDim.x + threadIdx.x;
    if (i < 32768) {
        int breg = i & 1;
        int lane = (i >> 1) & 31;
        int ntg  = (i >> 6) & 15;
        int kt   = (i >> 10) & 7;
        int m    = i >> 13;
        int t = lane & 3, nr = lane >> 2;
        int n = ntg * 8 + nr;
        int k = kt * 16 + 2 * t + breg * 8;
        const float* Wm = (m == 0) ? pw : (m == 1) ? w0 : (m == 2) ? w1 : w2;
        __half lo = __float2half(Wm[k * 128 + n]);
        __half hi = __float2half(Wm[(k + 1) * 128 + n]);
        __half2 h2 = __halves2half2(lo, hi);
        Wfrag[i] = *(unsigned*)&h2;
    } else if (i < 32768 + 768) {
        int j = i - 32768;
        int v = j >> 8;
        int rem = j & 255;
        int sd = rem >> 7;
        int c = rem & 127;
        const float* p;
        if (v == 0) p = sd ? ad0 : as0;
        else if (v == 1) p = sd ? ad1 : as1;
        else p = sd ? ad2 : as2;
        attc[j] = p[c];
    }
}

// ---------------- fused front: LN + proj + 3 view GEMMs + att coefs ----------------
__global__ void __launch_bounds__(256) fused_front_kernel(
    const float* __restrict__ x, const float* __restrict__ ln_g, const float* __restrict__ ln_b,
    const unsigned* __restrict__ Wfrag, const float* __restrict__ proj_b,
    const float* __restrict__ attc,
    __half* __restrict__ xh, float* __restrict__ asrc, float* __restrict__ adst, int n)
{
    __shared__ __align__(16) __half sH[64 * ROWH];
    int t = threadIdx.x;
    int lane = t & 31, w = t >> 5;
    int wr = w >> 2, wc = w & 3;
    int base = blockIdx.x * 64;

    // LN: warp w owns local nodes w*8..w*8+7; lane reads float4 at column lane*4
    {
        float4 lng = *(const float4*)(ln_g + lane * 4);
        float4 lnb = *(const float4*)(ln_b + lane * 4);
        #pragma unroll
        for (int jj = 0; jj < 8; jj++) {
            int j = w * 8 + jj;
            int node = base + j;
            float4 v = make_float4(0.f, 0.f, 0.f, 0.f);
            if (node < n) v = *(const float4*)(x + (size_t)node * 128 + lane * 4);
            float s = v.x + v.y + v.z + v.w;
            float q = v.x * v.x + v.y * v.y + v.z * v.z + v.w * v.w;
            #pragma unroll
            for (int o = 16; o; o >>= 1) {
                s += __shfl_xor_sync(0xffffffffu, s, o);
                q += __shfl_xor_sync(0xffffffffu, q, o);
            }
            float mu = s * (1.f / 128.f);
            float var = q * (1.f / 128.f) - mu * mu;
            float inv = rsqrtf(var + 1e-5f);
            float n0 = (v.x - mu) * inv * lng.x + lnb.x;
            float n1 = (v.y - mu) * inv * lng.y + lnb.y;
            float n2 = (v.z - mu) * inv * lng.z + lnb.z;
            float n3 = (v.w - mu) * inv * lng.w + lnb.w;
            __half2 h0 = __floats2half2_rn(n0, n1);
            __half2 h1 = __floats2half2_rn(n2, n3);
            uint2 pk;
            pk.x = *(unsigned*)&h0;
            pk.y = *(unsigned*)&h1;
            *(uint2*)(sH + j * ROWH + lane * 4) = pk;
        }
    }
    __syncthreads();

    uint32_t sH_u = (uint32_t)__cvta_generic_to_shared(sH);
    int g8 = lane >> 3;
    int lrow = (lane & 7) + ((g8 & 1) << 3);
    int koff = (g8 >> 1) << 3;
    uint32_t abase[2];
    abase[0] = sH_u + (uint32_t)(((wr * 32 + lrow) * ROWH + koff) * 2);
    abase[1] = sH_u + (uint32_t)(((wr * 32 + 16 + lrow) * ROWH + koff) * 2);

    float acc[8][4];

    // ---- GEMM 1: proj ----
    {
        #pragma unroll
        for (int i = 0; i < 8; i++) { acc[i][0] = acc[i][1] = acc[i][2] = acc[i][3] = 0.f; }
        const unsigned* WF = Wfrag;
        #pragma unroll
        for (int kt = 0; kt < 8; kt++) {
            unsigned a[2][4];
            ldsm_x4(a[0], abase[0] + kt * 32);
            ldsm_x4(a[1], abase[1] + kt * 32);
            uint2 b[4];
            #pragma unroll
            for (int nt = 0; nt < 4; nt++)
                b[nt] = *(const uint2*)&WF[(kt * 16 + (wc * 4 + nt)) * 64 + lane * 2];
            #pragma unroll
            for (int mt = 0; mt < 2; mt++)
                #pragma unroll
                for (int nt = 0; nt < 4; nt++)
                    mma_f16(acc[mt * 4 + nt], a[mt], (const unsigned*)&b[nt]);
        }
    }
    __syncthreads();

    #pragma unroll
    for (int mt = 0; mt < 2; mt++) {
        #pragma unroll
        for (int nt = 0; nt < 4; nt++) {
            float* c = acc[mt * 4 + nt];
            int r0 = wr * 32 + mt * 16 + (lane >> 2);
            int c0 = wc * 32 + nt * 8 + (lane & 3) * 2;
            float pb0 = proj_b[c0], pb1 = proj_b[c0 + 1];
            float v0 = c[0] + pb0, v1 = c[1] + pb1, v2 = c[2] + pb0, v3 = c[3] + pb1;
            v0 = (v0 > 0.f) ? v0 : 0.01f * v0;
            v1 = (v1 > 0.f) ? v1 : 0.01f * v1;
            v2 = (v2 > 0.f) ? v2 : 0.01f * v2;
            v3 = (v3 > 0.f) ? v3 : 0.01f * v3;
            *(__half2*)(sH + r0 * ROWH + c0) = __floats2half2_rn(v0, v1);
            *(__half2*)(sH + (r0 + 8) * ROWH + c0) = __floats2half2_rn(v2, v3);
        }
    }
    __syncthreads();

    for (int v = 0; v < 3; v++) {
        const unsigned* WF = Wfrag + (v + 1) * 8192;
        #pragma unroll
        for (int i = 0; i < 8; i++) { acc[i][0] = acc[i][1] = acc[i][2] = acc[i][3] = 0.f; }
        #pragma unroll
        for (int kt = 0; kt < 8; kt++) {
            unsigned a[2][4];
            ldsm_x4(a[0], abase[0] + kt * 32);
            ldsm_x4(a[1], abase[1] + kt * 32);
            uint2 b[4];
            #pragma unroll
            for (int nt = 0; nt < 4; nt++)
                b[nt] = *(const uint2*)&WF[(kt * 16 + (wc * 4 + nt)) * 64 + lane * 2];
            #pragma unroll
            for (int mt = 0; mt < 2; mt++)
                #pragma unroll
                for (int nt = 0; nt < 4; nt++)
                    mma_f16(acc[mt * 4 + nt], a[mt], (const unsigned*)&b[nt]);
        }

        const float* attS = attc + v * 256;
        const float* attD = attS + 128;
        __half* xh_v = xh + (size_t)v * XH_STRIDE;
        float ps[4] = {0.f, 0.f, 0.f, 0.f}, pd[4] = {0.f, 0.f, 0.f, 0.f};
        #pragma unroll
        for (int mt = 0; mt < 2; mt++) {
            #pragma unroll
            for (int nt = 0; nt < 4; nt++) {
                float* c = acc[mt * 4 + nt];
                int r0 = wr * 32 + mt * 16 + (lane >> 2);
                int c0 = wc * 32 + nt * 8 + (lane & 3) * 2;
                int node0 = base + r0, node1 = base + r0 + 8;
                if (node0 < n)
                    *(__half2*)(xh_v + (size_t)node0 * 128 + c0) = __floats2half2_rn(c[0], c[1]);
                if (node1 < n)
                    *(__half2*)(xh_v + (size_t)node1 * 128 + c0) = __floats2half2_rn(c[2], c[3]);
                float s0 = attS[c0], s1 = attS[c0 + 1];
                float d0 = attD[c0], d1 = attD[c0 + 1];
                ps[mt * 2 + 0] += c[0] * s0 + c[1] * s1;
                ps[mt * 2 + 1] += c[2] * s0 + c[3] * s1;
                pd[mt * 2 + 0] += c[0] * d0 + c[1] * d1;
                pd[mt * 2 + 1] += c[2] * d0 + c[3] * d1;
            }
        }
        float* asrc_v = asrc + v * NMAX * 4;
        float* adst_v = adst + v * NMAX * 4;
        #pragma unroll
        for (int idx = 0; idx < 4; idx++) {
            float s = ps[idx], d = pd[idx];
            s += __shfl_xor_sync(0xffffffffu, s, 1);
            s += __shfl_xor_sync(0xffffffffu, s, 2);
            d += __shfl_xor_sync(0xffffffffu, d, 1);
            d += __shfl_xor_sync(0xffffffffu, d, 2);
            if ((lane & 3) == 0) {
                int mt = idx >> 1, half = idx & 1;
                int node = base + wr * 32 + mt * 16 + (lane >> 2) + half * 8;
                if (node < n) {
                    asrc_v[node * 4 + wc] = s;
                    adst_v[node * 4 + wc] = d;
                }
            }
        }
    }
}

// ---------------- CSR build ----------------
__global__ void zero_kernel(int4* cnt4, int n4, int4* flags4, int f4) {
    int i = blockIdx.x * blockDim.x + threadIdx.x;
    int4 z = make_int4(0, 0, 0, 0);
    if (i < n4) cnt4[i] = z;
    if (i < f4) flags4[i] = z;
}

// 4 edges per thread via int4
__global__ void hist3_kernel(const int* __restrict__ e0, const int* __restrict__ e1,
                             const int* __restrict__ e2, int e, int* __restrict__ cnt)
{
    int v = blockIdx.y;
    const int* dst = ((v == 0) ? e0 : (v == 1) ? e1 : e2) + e;
    int* cv = cnt + v * NMAX;
    int i = blockIdx.x * blockDim.x + threadIdx.x;
    int base = i * 4;
    if (base + 3 < e && ((e & 3) == 0)) {
        int4 d4 = __ldcs(&((const int4*)dst)[i]);
        atomicAdd(&cv[d4.x], 1);
        atomicAdd(&cv[d4.y], 1);
        atomicAdd(&cv[d4.z], 1);
        atomicAdd(&cv[d4.w], 1);
    } else {
        for (int k = base; k < e && k < base + 4; k++) atomicAdd(&cv[dst[k]], 1);
    }
}

// ---------------- single-kernel decoupled-lookback scan ----------------
__global__ void __launch_bounds__(256) scan_lookback_kernel(
    const int4* __restrict__ c4, int n4,
    int* __restrict__ start, int* __restrict__ cursor,
    int* flag_, int* agg_, int* pfx_)
{
    volatile int* flag = (volatile int*)flag_;
    volatile int* agg  = (volatile int*)agg_;
    volatile int* pfx  = (volatile int*)pfx_;
    __shared__ int wsum[8];
    __shared__ int s_total;
    __shared__ int s_excl;

    int b = blockIdx.x;
    int t = threadIdx.x, lane = t & 31, w = t >> 5;
    int i = b * 256 + t;
    int4 v = make_int4(0, 0, 0, 0);
    if (i < n4) v = c4[i];
    int s = v.x + v.y + v.z + v.w;
    int incl = s;
    #pragma unroll
    for (int o = 1; o < 32; o <<= 1) {
        int u = __shfl_up_sync(0xffffffffu, incl, o);
        if (lane >= o) incl += u;
    }
    if (lane == 31) wsum[w] = incl;
    if (t == 0) s_excl = 0;
    __syncthreads();
    if (w == 0 && lane < 8) {
        int sv = wsum[lane];
        int si = sv;
        #pragma unroll
        for (int o = 1; o < 8; o <<= 1) {
            int u = __shfl_up_sync(0x000000ffu, si, o);
            if (lane >= o) si += u;
        }
        wsum[lane] = si - sv;
        if (lane == 7) s_total = si;
    }
    __syncthreads();
    int total = s_total;

    if (w == 0) {
        if (b == 0) {
            if (lane == 0) {
                pfx_[0] = total;
                __threadfence();
                flag_[0] = 2;
            }
        } else {
            if (lane == 0) {
                agg_[b] = total;
                __threadfence();
                flag_[b] = 1;
            }
            __syncwarp();
            int excl = 0;
            int pos = b - 1;
            while (true) {
                int idx = pos - lane;
                int f;
                do {
                    f = (idx >= 0) ? flag[idx] : 2;
                } while (!__all_sync(0xffffffffu, f >= 1));
                __threadfence();
                int vv = 0;
                if (idx >= 0) vv = (f == 2) ? pfx[idx] : agg[idx];
                unsigned pmask = __ballot_sync(0xffffffffu, f == 2);
                if (pmask) {
                    int k = __ffs(pmask) - 1;
                    int contrib = (lane <= k) ? vv : 0;
                    #pragma unroll
                    for (int o = 16; o; o >>= 1)
                        contrib += __shfl_xor_sync(0xffffffffu, contrib, o);
                    excl += contrib;
                    break;
                } else {
                    int contrib = vv;
                    #pragma unroll
                    for (int o = 16; o; o >>= 1)
                        contrib += __shfl_xor_sync(0xffffffffu, contrib, o);
                    excl += contrib;
                    pos -= 32;
                }
            }
            if (lane == 0) {
                s_excl = excl;
                pfx_[b] = excl + total;
                __threadfence();
                flag_[b] = 2;
            }
        }
    }
    __syncthreads();

    if (i < n4) {
        int off = s_excl + wsum[w] + (incl - s);
        int o0 = off, o1 = off + v.x, o2 = o1 + v.y, o3 = o2 + v.z;
        start[4 * i] = o0; start[4 * i + 1] = o1; start[4 * i + 2] = o2; start[4 * i + 3] = o3;
        cursor[4 * i] = o0; cursor[4 * i + 1] = o1; cursor[4 * i + 2] = o2; cursor[4 * i + 3] = o3;
    }
}

// 4 edges per thread via int4 (src + dst)
__global__ void scatter3_kernel(const int* __restrict__ e0, const int* __restrict__ e1,
                                const int* __restrict__ e2, int e,
                                int* __restrict__ cursor, int* __restrict__ col)
{
    int v = blockIdx.y;
    const int* ei = (v == 0) ? e0 : (v == 1) ? e1 : e2;
    int* cv = cursor + v * NMAX;
    int i = blockIdx.x * blockDim.x + threadIdx.x;
    int base = i * 4;
    if (base + 3 < e && ((e & 3) == 0)) {
        int4 s4 = __ldcs(&((const int4*)ei)[i]);
        int4 d4 = __ldcs(&((const int4*)(ei + e))[i]);
        int p0 = atomicAdd(&cv[d4.x], 1);
        int p1 = atomicAdd(&cv[d4.y], 1);
        int p2 = atomicAdd(&cv[d4.z], 1);
        int p3 = atomicAdd(&cv[d4.w], 1);
        col[p0] = s4.x;
        col[p1] = s4.y;
        col[p2] = s4.z;
        col[p3] = s4.w;
    } else {
        for (int k = base; k < e && k < base + 4; k++) {
            int d = ei[e + k];
            int p = atomicAdd(&cv[d], 1);
            col[p] = ei[k];
        }
    }
}

// ---------------- GAT aggregation (fp16, 8-wide, warp per destination) ----------------
__global__ void gat_aggregate_kernel(
    const __half* __restrict__ xh, const float* __restrict__ asrc, const float* __restrict__ adst,
    const int* __restrict__ start, const int* __restrict__ cnt, const int* __restrict__ col,
    const float* __restrict__ bias, const float* __restrict__ gate_W, const float* __restrict__ gate_b,
    __half* __restrict__ hv, float* __restrict__ eg, int n)
{
    int d = (blockIdx.x * blockDim.x + threadIdx.x) >> 5;
    int lane = threadIdx.x & 31;
    if (d >= n) return;
    int h = lane >> 3;
    const uint2* xh2 = (const uint2*)xh;

    float ad = adst[d * 4 + h];
    float as = asrc[d * 4 + h];
    float l = as + ad; l = (l > 0.f) ? l : 0.2f * l;
    float wv = __expf(l);
    float denom = wv;
    uint2 selfr = xh2[(size_t)d * 32 + lane];
    float2 sf0 = __half22float2(*(const __half2*)&selfr.x);
    float2 sf1 = __half22float2(*(const __half2*)&selfr.y);
    float4 acc = make_float4(wv * sf0.x, wv * sf0.y, wv * sf1.x, wv * sf1.y);

    int s0 = start[d];
    int c = cnt[d];

    int e = 0;
    for (; e + 8 <= c; e += 8) {
        int s_[8];
        #pragma unroll
        for (int j = 0; j < 8; j++) s_[j] = __ldcs(&col[s0 + e + j]);
        float a_[8];
        uint2 u_[8];
        #pragma unroll
        for (int j = 0; j < 8; j++) {
            a_[j] = asrc[s_[j] * 4 + h];
            u_[j] = xh2[(size_t)s_[j] * 32 + lane];
        }
        #pragma unroll
        for (int j = 0; j < 8; j++) {
            float lg = a_[j] + ad; lg = (lg > 0.f) ? lg : 0.2f * lg;
            float we = __expf(lg);
            denom += we;
            float2 f0 = __half22float2(*(const __half2*)&u_[j].x);
            float2 f1 = __half22float2(*(const __half2*)&u_[j].y);
            acc.x += we * f0.x; acc.y += we * f0.y;
            acc.z += we * f1.x; acc.w += we * f1.y;
        }
    }
    for (; e < c; e++) {
        int s = __ldcs(&col[s0 + e]);
        float a = asrc[s * 4 + h];
        uint2 u = xh2[(size_t)s * 32 + lane];
        float lg = a + ad; lg = (lg > 0.f) ? lg : 0.2f * lg;
        float we = __expf(lg);
        denom += we;
        float2 f0 = __half22float2(*(const __half2*)&u.x);
        float2 f1 = __half22float2(*(const __half2*)&u.y);
        acc.x += we * f0.x; acc.y += we * f0.y;
        acc.z += we * f1.x; acc.w += we * f1.y;
    }

    float inv = 1.f / denom;
    float4 b4 = ((const float4*)bias)[lane];
    float4 o;
    o.x = acc.x * inv + b4.x;
    o.y = acc.y * inv + b4.y;
    o.z = acc.z * inv + b4.z;
    o.w = acc.w * inv + b4.w;
    o.x = (o.x > 0.f) ? o.x : (__expf(o.x) - 1.f);
    o.y = (o.y > 0.f) ? o.y : (__expf(o.y) - 1.f);
    o.z = (o.z > 0.f) ? o.z : (__expf(o.z) - 1.f);
    o.w = (o.w > 0.f) ? o.w : (__expf(o.w) - 1.f);
    __half2 ho0 = __floats2half2_rn(o.x, o.y);
    __half2 ho1 = __floats2half2_rn(o.z, o.w);
    unsigned w0 = *(const unsigned*)&ho0;
    unsigned w1 = *(const unsigned*)&ho1;
    asm volatile("st.global.cs.v2.u32 [%0], {%1, %2};"
                 :: "l"(hv + (size_t)d * 128 + lane * 4), "r"(w0), "r"(w1) : "memory");

    float4 g4 = ((const float4*)gate_W)[lane];
    float p = o.x * g4.x + o.y * g4.y + o.z * g4.z + o.w * g4.w;
    #pragma unroll
    for (int off = 16; off; off >>= 1) p += __shfl_xor_sync(0xffffffffu, p, off);
    if (lane == 0) eg[d] = __expf(p + gate_b[0]);
}

// ---------------- graph boundaries ----------------
__global__ void bounds_kernel(const int* __restrict__ batch, int n, int nb,
                              int* __restrict__ gs, int* __restrict__ ge)
{
    int b = blockIdx.x * blockDim.x + threadIdx.x;
    if (b >= nb) return;
    int lo = 0, hi = n;
    while (lo < hi) { int mid = (lo + hi) >> 1; if (batch[mid] < b) lo = mid + 1; else hi = mid; }
    gs[b] = lo;
    lo = 0; hi = n;
    while (lo < hi) { int mid = (lo + hi) >> 1; if (batch[mid] < b + 1) lo = mid + 1; else hi = mid; }
    ge[b] = lo;
}

// ---------------- pooling: 8-wide MLP batching ----------------
__global__ void __launch_bounds__(128) pool3_kernel(
    const __half* __restrict__ hv, const float* __restrict__ eg,
    const int* __restrict__ gs, const int* __restrict__ ge,
    float* __restrict__ combined)
{
    int b = blockIdx.x, v = blockIdx.y, t = threadIdx.x;
    const __half* hv_v = hv + (size_t)v * XH_STRIDE;
    const float* eg_v = eg + v * NMAX;
    int s = gs[b], e2 = ge[b];
    float denom = 0.f, acc = 0.f;
    int i = s;
    for (; i + 8 <= e2; i += 8) {
        float w_[8];
        __half h_[8];
        #pragma unroll
        for (int j = 0; j < 8; j++) w_[j] = eg_v[i + j];
        #pragma unroll
        for (int j = 0; j < 8; j++) h_[j] = hv_v[(size_t)(i + j) * 128 + t];
        #pragma unroll
        for (int j = 0; j < 8; j++) {
            denom += w_[j];
            acc += w_[j] * __half2float(h_[j]);
        }
    }
    for (; i < e2; i++) {
        float w = eg_v[i];
        denom += w;
        acc += w * __half2float(hv_v[(size_t)i * 128 + t]);
    }
    combined[(size_t)b * 384 + v * 128 + t] = (e2 > s) ? (acc / denom) : 0.f;
}

// ---------------- classifier ----------------
__global__ void __launch_bounds__(128) classifier_kernel(
    const float* __restrict__ comb, const float* __restrict__ W1, const float* __restrict__ b1,
    const float* __restrict__ W2, const float* __restrict__ b2, float* __restrict__ out)
{
    __shared__ float cs[384];
    __shared__ float red[4];
    int b = blockIdx.x, t = threadIdx.x;
    for (int i = t; i < 384; i += 128) cs[i] = comb[(size_t)b * 384 + i];
    __syncthreads();
    float acc = b1[t];
    for (int k = 0; k < 384; k++) acc += cs[k] * W1[k * 128 + t];
    acc = (acc > 0.f) ? acc : 0.01f * acc;
    float v = acc * W2[t];
    #pragma unroll
    for (int o = 16; o; o >>= 1) v += __shfl_xor_sync(0xffffffffu, v, o);
    if ((t & 31) == 0) red[t >> 5] = v;
    __syncthreads();
    if (t == 0) out[b] = red[0] + red[1] + red[2] + red[3] + b2[0];
}

// ---------------- launch ----------------
template <typename T>
static T* sym_addr(const void* sym) {
    void* p = nullptr;
    cudaGetSymbolAddress(&p, sym);
    return (T*)p;
}

extern "C" void kernel_launch(void* const* d_in, const int* in_sizes, int n_in,
                              void* d_out, int out_size)
{
    const float* x      = (const float*)d_in[0];
    const int*   e0     = (const int*)d_in[1];
    const int*   e1     = (const int*)d_in[2];
    const int*   e2     = (const int*)d_in[3];
    const int*   batch  = (const int*)d_in[4];
    const float* ln_g   = (const float*)d_in[5];
    const float* ln_b   = (const float*)d_in[6];
    const float* proj_W = (const float*)d_in[7];
    const float* proj_b = (const float*)d_in[8];
    const float* Wv[3]    = {(const float*)d_in[9],  (const float*)d_in[13], (const float*)d_in[17]};
    const float* asv[3]   = {(const float*)d_in[10], (const float*)d_in[14], (const float*)d_in[18]};
    const float* adv[3]   = {(const float*)d_in[11], (const float*)d_in[15], (const float*)d_in[19]};
    const float* biasv[3] = {(const float*)d_in[12], (const float*)d_in[16], (const float*)d_in[20]};
    const float* gate_W = (const float*)d_in[21];
    const float* gate_b = (const float*)d_in[22];
    const float* clf_W1 = (const float*)d_in[23];
    const float* clf_b1 = (const float*)d_in[24];
    const float* clf_W2 = (const float*)d_in[25];
    const float* clf_b2 = (const float*)d_in[26];
    float* out = (float*)d_out;

    int n  = in_sizes[0] / 128;
    int e  = in_sizes[1] / 2;
    int nb = out_size;

    __half* xh   = sym_addr<__half>(g_xh);
    __half* hv   = sym_addr<__half>(g_hv);
    float* asrc  = sym_addr<float>(g_asrc);
    float* adst  = sym_addr<float>(g_adst);
    float* eg    = sym_addr<float>(g_eg);
    int*   cnt   = sym_addr<int>(g_cnt);
    int*   strt  = sym_addr<int>(g_start);
    int*   curs  = sym_addr<int>(g_cursor);
    int*   col   = sym_addr<int>(g_col);
    int*   gs    = sym_addr<int>(g_gs);
    int*   ge    = sym_addr<int>(g_ge);
    float* comb  = sym_addr<float>(g_combined);
    unsigned* Wfrag = sym_addr<unsigned>(g_Wfrag16);
    float* attc  = sym_addr<float>(g_attc);
    int*   sflag = sym_addr<int>(g_scan_flag);
    int*   sagg  = sym_addr<int>(g_scan_agg);
    int*   spfx  = sym_addr<int>(g_scan_pfx);

    int node_tiles  = (n + 63) / 64;
    int warp_blocks = (n + 7) / 8;
    int edge4_blocks = ((e + 3) / 4 + 255) / 256;

    const int T  = 3 * NMAX;
    const int n4 = T / 4;
    const int sblocks = (n4 + 255) / 256;

    // Fork a side stream so the (prep -> front) chain runs CONCURRENTLY with the
    // CSR-build chain (zero -> hist -> scan -> scatter). The two chains are
    // data-independent and resource-complementary (tensor/L1 vs L2-atomics).
    // Stream/events are created per call and intentionally NOT destroyed here:
    // destroying a capture-participating stream before EndCapture invalidates the
    // capture, and kernel_launch only runs a handful of times (no device memory).
    cudaStream_t s2;
    cudaStreamCreateWithFlags(&s2, cudaStreamNonBlocking);
    cudaEvent_t evFork, evJoin;
    cudaEventCreateWithFlags(&evFork, cudaEventDisableTiming);
    cudaEventCreateWithFlags(&evJoin, cudaEventDisableTiming);

    cudaEventRecord(evFork, 0);
    cudaStreamWaitEvent(s2, evFork, 0);

    // branch B: weights/att prep, bounds, fused front
    prep_kernel<<<(32768 + 768 + 255) / 256, 256, 0, s2>>>(
        proj_W, Wv[0], Wv[1], Wv[2],
        asv[0], adv[0], asv[1], adv[1], asv[2], adv[2], Wfrag, attc);
    bounds_kernel<<<(nb + 255) / 256, 256, 0, s2>>>(batch, n, nb, gs, ge);
    fused_front_kernel<<<node_tiles, 256, 0, s2>>>(x, ln_g, ln_b, Wfrag, proj_b, attc,
                                                   xh, asrc, adst, n);
    cudaEventRecord(evJoin, s2);

    // branch A (capture stream): CSR build
    zero_kernel<<<(n4 + 255) / 256, 256>>>((int4*)cnt, n4, (int4*)sflag, 128);
    hist3_kernel<<<dim3(edge4_blocks, 3), 256>>>(e0, e1, e2, e, cnt);
    scan_lookback_kernel<<<sblocks, 256>>>((const int4*)cnt, n4, strt, curs,
                                           sflag, sagg, spfx);
    scatter3_kernel<<<dim3(edge4_blocks, 3), 256>>>(e0, e1, e2, e, curs, col);

    // join: aggregation needs both branches
    cudaStreamWaitEvent(0, evJoin, 0);

    // sequential per-view aggregation (start[] holds GLOBAL col offsets; col UNOFFSET)
    for (int v = 0; v < 3; v++) {
        gat_aggregate_kernel<<<warp_blocks, 256>>>(
            xh + (size_t)v * XH_STRIDE, asrc + v * NMAX * 4, adst + v * NMAX * 4,
            strt + v * NMAX, cnt + v * NMAX, col,
            biasv[v], gate_W, gate_b,
            hv + (size_t)v * XH_STRIDE, eg + v * NMAX, n);
    }

    pool3_kernel<<<dim3(nb, 3), 128>>>(hv, eg, gs, ge, comb);
    classifier_kernel<<<nb, 128>>>(comb, clf_W1, clf_b1, clf_W2, clf_b2, out);
}